// round 11
// baseline (speedup 1.0000x reference)
#include <cuda_runtime.h>
#include <cuda_fp16.h>
#include <cstdint>

#define BATCH 8
#define NUM_PM 300
#define NUM_VM 1000
#define PM_COV 8
#define DMODEL 256
#define NHEAD 8
#define DHEAD 32
#define DFF 1024
#define NLAYER 3
#define SEQL (NUM_PM + NUM_VM + 2)   // 1302
#define MROWS (BATCH * SEQL)          // 10416
#define CAP 64

// ---------------- static scratch ----------------
__device__ float  g_x[MROWS * DMODEL];
__device__ __half g_h[MROWS * DMODEL];
__device__ float  g_q[MROWS * DMODEL];
__device__ float  g_k[MROWS * DMODEL];
__device__ float  g_v[MROWS * DMODEL];
__device__ __half g_o[MROWS * DMODEL];
__device__ __half g_ffn[MROWS * DFF];
__device__ int    g_rel[MROWS];
__device__ int    g_cnt[BATCH * NUM_PM];
__device__ int    g_list[BATCH * NUM_PM * CAP];
// transposed + fp16 weights, [N][K] K-major
__device__ __half g_Wqt[NLAYER * DMODEL * DMODEL];
__device__ __half g_Wkt[NLAYER * DMODEL * DMODEL];
__device__ __half g_Wvt[NLAYER * DMODEL * DMODEL];
__device__ __half g_Wot[NLAYER * DMODEL * DMODEL];
__device__ __half g_W1t[NLAYER * DMODEL * DFF];
__device__ __half g_W2t[NLAYER * DFF * DMODEL];

__device__ __forceinline__ uint32_t h2_u32(__half2 h) {
    union { __half2 h2; uint32_t u; } cv;
    cv.h2 = h;
    return cv.u;
}

// ---------------- embed + rel ----------------
__global__ void embed_kernel(const float* __restrict__ vm_states,
                             const float* __restrict__ num_step,
                             const float* __restrict__ pm_states,
                             const float* __restrict__ W_pm, const float* __restrict__ b_pm,
                             const float* __restrict__ W_vm, const float* __restrict__ b_vm,
                             const float* __restrict__ critic) {
    int b = blockIdx.y;
    int l = blockIdx.x;
    int d = threadIdx.x;
    float val;
    if (l == 0) {
        val = num_step[b];
    } else if (l <= NUM_PM) {
        const float* pm = pm_states + (b * NUM_PM + (l - 1)) * PM_COV;
        float acc = b_pm[d];
        #pragma unroll
        for (int c = 0; c < PM_COV; c++) acc += pm[c] * W_pm[c * DMODEL + d];
        val = acc;
    } else if (l <= NUM_PM + NUM_VM) {
        const float* vm = vm_states + (b * NUM_VM + (l - 1 - NUM_PM)) * 7;
        float acc = b_vm[d];
        #pragma unroll
        for (int c = 0; c < 6; c++) acc += vm[c] * W_vm[c * DMODEL + d];
        val = acc;
    } else {
        val = critic[d];
    }
    g_x[(b * SEQL + l) * DMODEL + d] = val;
    if (d == 0) {
        int r = -100;
        if (l >= 1 && l <= NUM_PM) r = l - 1;
        else if (l > NUM_PM && l < SEQL - 1)
            r = (int)vm_states[(b * NUM_VM + (l - 1 - NUM_PM)) * 7 + 6];
        g_rel[b * SEQL + l] = r;
    }
}

// ---------------- group list build ----------------
__global__ void build_init() {
    int i = blockIdx.x * 256 + threadIdx.x;
    if (i >= BATCH * NUM_PM) return;
    int r = i % NUM_PM;
    g_cnt[i] = 1;
    g_list[i * CAP] = 1 + r;
}

__global__ void build_vm(const float* __restrict__ vm_states) {
    int i = blockIdx.x * 256 + threadIdx.x;
    if (i >= BATCH * NUM_VM) return;
    int b = i / NUM_VM, j = i % NUM_VM;
    int r = (int)vm_states[(b * NUM_VM + j) * 7 + 6];
    int p = atomicAdd(&g_cnt[b * NUM_PM + r], 1);
    if (p < CAP) g_list[(b * NUM_PM + r) * CAP + p] = NUM_PM + 1 + j;
}

// ---------------- fused weight transpose + fp16: all 6 weights, one launch ----------------
__global__ void transpose_all(const float* __restrict__ Wq, const float* __restrict__ Wk,
                              const float* __restrict__ Wv, const float* __restrict__ Wo,
                              const float* __restrict__ W1, const float* __restrict__ W2) {
    __shared__ float t[32][33];
    int bid = blockIdx.x;
    const float* src;
    __half* dst;
    int K, N, ti;
    if (bid < 768) {
        int w = bid / 192;
        ti = bid % 192;
        src = (w == 0) ? Wq : (w == 1) ? Wk : (w == 2) ? Wv : Wo;
        dst = (w == 0) ? g_Wqt : (w == 1) ? g_Wkt : (w == 2) ? g_Wvt : g_Wot;
        K = DMODEL; N = DMODEL;
    } else if (bid < 1536) {
        ti = bid - 768; src = W1; dst = g_W1t; K = DMODEL; N = DFF;
    } else {
        ti = bid - 1536; src = W2; dst = g_W2t; K = DFF; N = DMODEL;
    }
    int tilesN = N >> 5;
    int perLayer = (K >> 5) * tilesN;
    int layer = ti / perLayer;
    int tt = ti - layer * perLayer;
    int k0 = (tt / tilesN) << 5, n0 = (tt % tilesN) << 5;
    const float* s = src + layer * K * N;
    __half* d = dst + layer * K * N;
    int tx = threadIdx.x, ty = threadIdx.y;
    #pragma unroll
    for (int j = 0; j < 32; j += 8)
        t[ty + j][tx] = s[(k0 + ty + j) * N + n0 + tx];
    __syncthreads();
    #pragma unroll
    for (int j = 0; j < 32; j += 8)
        d[(n0 + ty + j) * K + k0 + tx] = __float2half(t[tx][ty + j]);
}

// ---------------- layernorm: warp per row, fp16 output ----------------
__global__ void ln_kernel(const float* __restrict__ gamma, const float* __restrict__ beta) {
    int row = blockIdx.x * 8 + (threadIdx.x >> 5);
    if (row >= MROWS) return;
    int lane = threadIdx.x & 31;
    const float4* xr = (const float4*)(g_x + row * DMODEL) + lane * 2;
    float4 a = xr[0], c4 = xr[1];
    float v8[8] = {a.x, a.y, a.z, a.w, c4.x, c4.y, c4.z, c4.w};
    float s = 0.f;
    #pragma unroll
    for (int t = 0; t < 8; t++) s += v8[t];
    #pragma unroll
    for (int o = 16; o > 0; o >>= 1) s += __shfl_xor_sync(0xffffffffu, s, o);
    float mean = s * (1.0f / DMODEL);
    float vs = 0.f;
    #pragma unroll
    for (int t = 0; t < 8; t++) { v8[t] -= mean; vs += v8[t] * v8[t]; }
    #pragma unroll
    for (int o = 16; o > 0; o >>= 1) vs += __shfl_xor_sync(0xffffffffu, vs, o);
    float r = rsqrtf(vs * (1.0f / DMODEL) + 1e-5f);
    const float4* gg = (const float4*)gamma + lane * 2;
    const float4* bb = (const float4*)beta + lane * 2;
    float4 g0 = gg[0], g1 = gg[1], b0 = bb[0], b1 = bb[1];
    float ge[8] = {g0.x, g0.y, g0.z, g0.w, g1.x, g1.y, g1.z, g1.w};
    float be[8] = {b0.x, b0.y, b0.z, b0.w, b1.x, b1.y, b1.z, b1.w};
    uint4 pack;
    pack.x = h2_u32(__floats2half2_rn(v8[0] * r * ge[0] + be[0], v8[1] * r * ge[1] + be[1]));
    pack.y = h2_u32(__floats2half2_rn(v8[2] * r * ge[2] + be[2], v8[3] * r * ge[3] + be[3]));
    pack.z = h2_u32(__floats2half2_rn(v8[4] * r * ge[4] + be[4], v8[5] * r * ge[5] + be[5]));
    pack.w = h2_u32(__floats2half2_rn(v8[6] * r * ge[6] + be[6], v8[7] * r * ge[7] + be[7]));
    *((uint4*)(g_h + row * DMODEL) + lane) = pack;
}

// ---------------- GELU (tanh approx) ----------------
__device__ __forceinline__ float gelu_f(float x) {
    float x3 = x * x * x;
    float t = tanhf(0.7978845608028654f * (x + 0.044715f * x3));
    return 0.5f * x * (1.0f + t);
}

// ================= fp16 mma.sync GEMM =================
// Block 128x128, 4 warps (2x2), warp tile 64x64, BK=64 halfs,
// 3-stage cp.async pipeline, single barrier per chunk.
// Fragment smem traffic now 64KB/chunk = 512 cyc = MMA 512 cyc (balanced 1:1).
#define BKh 64
#define HSTRIDE 72
#define A_STAGE_H (128 * HSTRIDE)              // 9216 halfs
#define STAGE_H   (2 * A_STAGE_H)              // A + B = 18432 halfs
#define NSTAGE 3
#define GEMM_SMEM_H (NSTAGE * STAGE_H * 2)     // 110592 bytes

__device__ __forceinline__ void cp16s(uint32_t saddr, const void* g) {
    asm volatile("cp.async.cg.shared.global [%0], [%1], 16;\n" :: "r"(saddr), "l"(g));
}
#define CP_COMMIT() asm volatile("cp.async.commit_group;\n" ::: "memory")
#define CP_WAIT(n)  asm volatile("cp.async.wait_group %0;\n" :: "n"(n) : "memory")
__device__ __forceinline__ uint32_t smem_u32(const void* p) {
    uint32_t a;
    asm("{ .reg .u64 t; cvta.to.shared.u64 t, %1; cvt.u32.u64 %0, t; }" : "=r"(a) : "l"(p));
    return a;
}

// z-dim selects among up to 3 weight/bias/output sets (QKV fusion).
__global__ void __launch_bounds__(128, 2)
gemm_h(const __half* __restrict__ A,
       const __half* __restrict__ Wt0, const __half* __restrict__ Wt1,
       const __half* __restrict__ Wt2,
       const float* __restrict__ bias0, const float* __restrict__ bias1,
       const float* __restrict__ bias2,
       void* __restrict__ C0, void* __restrict__ C1, void* __restrict__ C2,
       const float* __restrict__ res,
       int M, int N, int K, int act) {
    const __half* Wt  = (blockIdx.z == 0) ? Wt0   : (blockIdx.z == 1) ? Wt1   : Wt2;
    const float* bias = (blockIdx.z == 0) ? bias0 : (blockIdx.z == 1) ? bias1 : bias2;
    void* Cv          = (blockIdx.z == 0) ? C0    : (blockIdx.z == 1) ? C1    : C2;

    extern __shared__ __half smh[];
    const int tid = threadIdx.x;
    const int m0 = blockIdx.y * 128;
    const int n0 = blockIdx.x * 128;
    const int lane = tid & 31;
    const int warp = tid >> 5;
    const int wm = warp >> 1;          // 0..1
    const int wn = warp & 1;           // 0..1
    const int lq = lane >> 2;          // 0..7
    const int lr = lane & 3;           // 0..3

    float c[4][8][4];
    #pragma unroll
    for (int i = 0; i < 4; i++)
        #pragma unroll
        for (int j = 0; j < 8; j++)
            #pragma unroll
            for (int p = 0; p < 4; p++) c[i][j][p] = 0.f;

    uint32_t sb = smem_u32(smh);

    auto loadStage = [&](int stage, int ct) {
        int kc = ct * BKh;
        uint32_t offA = sb + stage * (STAGE_H * 2);
        uint32_t offB = offA + A_STAGE_H * 2;
        #pragma unroll
        for (int p = 0; p < 8; p++) {
            int i = tid + p * 128;
            int r = i >> 3, seg = i & 7;             // 8 segs of 8 halfs = 64 halfs
            int gm = m0 + r;
            if (gm >= M) gm = M - 1;
            cp16s(offA + (r * HSTRIDE + seg * 8) * 2, A + gm * K + kc + seg * 8);
            cp16s(offB + (r * HSTRIDE + seg * 8) * 2, Wt + (n0 + r) * K + kc + seg * 8);
        }
    };

    auto computeStage = [&](int stage) {
        const __half* As = smh + stage * STAGE_H;
        const __half* Bs = As + A_STAGE_H;
        #pragma unroll
        for (int kk = 0; kk < BKh; kk += 16) {
            uint32_t af[4][4], bf[8][2];
            #pragma unroll
            for (int tm = 0; tm < 4; tm++) {
                const __half* ap = As + (wm * 64 + tm * 16 + lq) * HSTRIDE + kk + 2 * lr;
                af[tm][0] = *(const uint32_t*)(ap);
                af[tm][1] = *(const uint32_t*)(ap + 8 * HSTRIDE);
                af[tm][2] = *(const uint32_t*)(ap + 8);
                af[tm][3] = *(const uint32_t*)(ap + 8 * HSTRIDE + 8);
            }
            #pragma unroll
            for (int tn = 0; tn < 8; tn++) {
                const __half* bp = Bs + (wn * 64 + tn * 8 + lq) * HSTRIDE + kk + 2 * lr;
                bf[tn][0] = *(const uint32_t*)(bp);
                bf[tn][1] = *(const uint32_t*)(bp + 8);
            }
            #pragma unroll
            for (int tm = 0; tm < 4; tm++)
                #pragma unroll
                for (int tn = 0; tn < 8; tn++) {
                    asm volatile(
                        "mma.sync.aligned.m16n8k16.row.col.f32.f16.f16.f32 "
                        "{%0,%1,%2,%3}, {%4,%5,%6,%7}, {%8,%9}, {%0,%1,%2,%3};\n"
                        : "+f"(c[tm][tn][0]), "+f"(c[tm][tn][1]),
                          "+f"(c[tm][tn][2]), "+f"(c[tm][tn][3])
                        : "r"(af[tm][0]), "r"(af[tm][1]), "r"(af[tm][2]), "r"(af[tm][3]),
                          "r"(bf[tn][0]), "r"(bf[tn][1]));
                }
        }
    };

    const int KT = K / BKh;
    // Single-barrier 3-stage pipeline (R10-proven ordering):
    //   prefetch ct+1, wait own groups (chunk ct landed), __syncthreads for
    //   cross-thread visibility, then compute chunk ct.
    loadStage(0, 0);
    CP_COMMIT();
    for (int ct = 0; ct < KT; ct++) {
        if (ct + 1 < KT) {
            loadStage((ct + 1) % NSTAGE, ct + 1);
            CP_COMMIT();
            CP_WAIT(1);
        } else {
            CP_WAIT(0);
        }
        __syncthreads();
        computeStage(ct % NSTAGE);
    }

    // epilogue
    #pragma unroll
    for (int tm = 0; tm < 4; tm++) {
        #pragma unroll
        for (int tn = 0; tn < 8; tn++) {
            int row0 = m0 + wm * 64 + tm * 16 + lq;
            int col = n0 + wn * 64 + tn * 8 + 2 * lr;
            #pragma unroll
            for (int half_i = 0; half_i < 2; half_i++) {
                int r = row0 + half_i * 8;
                if (r < M) {
                    float v0 = c[tm][tn][half_i * 2 + 0] + bias[col];
                    float v1 = c[tm][tn][half_i * 2 + 1] + bias[col + 1];
                    if (res) { v0 += res[r * N + col]; v1 += res[r * N + col + 1]; }
                    if (act) {
                        __half2 hv = __floats2half2_rn(gelu_f(v0), gelu_f(v1));
                        *(__half2*)((__half*)Cv + r * N + col) = hv;
                    } else {
                        float* C = (float*)Cv;
                        C[r * N + col] = v0;
                        C[r * N + col + 1] = v1;
                    }
                }
            }
        }
    }
}

// ---------------- sparse attention: warp per (b, query), fp16 output ----------------
__global__ void attn_kernel() {
    int gw = blockIdx.x * 8 + (threadIdx.x >> 5);
    if (gw >= BATCH * SEQL) return;
    int b = gw / SEQL;
    int l = gw - b * SEQL;
    int lane = threadIdx.x & 31;
    int row = b * SEQL + l;

    if (l == 0 || l == SEQL - 1) {
        #pragma unroll
        for (int t = 0; t < 8; t++)
            g_o[row * DMODEL + lane + 32 * t] = __float2half(g_v[row * DMODEL + lane + 32 * t]);
        return;
    }

    int r = g_rel[row];
    int cnt = g_cnt[b * NUM_PM + r];
    if (cnt > CAP) cnt = CAP;
    const int* lst = g_list + (b * NUM_PM + r) * CAP;

    const float scale = 0.17677669529663687f;
    float q8[8], o8[8], mx[8], sum[8];
    #pragma unroll
    for (int h = 0; h < 8; h++) {
        q8[h] = g_q[row * DMODEL + lane + 32 * h] * scale;
        o8[h] = 0.f; mx[h] = -1e30f; sum[h] = 0.f;
    }

    for (int i = 0; i < cnt; i++) {
        int krow = b * SEQL + lst[i];
        float k8[8], v8[8];
        #pragma unroll
        for (int t = 0; t < 8; t++) {
            k8[t] = g_k[krow * DMODEL + lane + 32 * t];
            v8[t] = g_v[krow * DMODEL + lane + 32 * t];
        }
        #pragma unroll
        for (int h = 0; h < 8; h++) {
            float d = q8[h] * k8[h];
            #pragma unroll
            for (int o = 16; o > 0; o >>= 1) d += __shfl_xor_sync(0xffffffffu, d, o);
            float nm = fmaxf(mx[h], d);
            float corr = __expf(mx[h] - nm);
            float p = __expf(d - nm);
            sum[h] = sum[h] * corr + p;
            o8[h] = o8[h] * corr + p * v8[h];
            mx[h] = nm;
        }
    }
    #pragma unroll
    for (int h = 0; h < 8; h++)
        g_o[row * DMODEL + lane + 32 * h] = __float2half(o8[h] / sum[h]);
}

// ---------------- output head ----------------
__global__ void out_kernel(const float* __restrict__ W_out, const float* __restrict__ b_out,
                           float* __restrict__ out) {
    int b = blockIdx.y;
    int warp = threadIdx.x >> 5;
    int lane = threadIdx.x & 31;
    int j = blockIdx.x * 8 + warp;
    if (j >= NUM_VM) return;
    int row = b * SEQL + NUM_PM + 1 + j;
    float acc = 0.f;
    #pragma unroll
    for (int d = lane; d < DMODEL; d += 32)
        acc += g_x[row * DMODEL + d] * W_out[d];
    #pragma unroll
    for (int o = 16; o > 0; o >>= 1) acc += __shfl_xor_sync(0xffffffffu, acc, o);
    if (lane == 0) out[b * NUM_VM + j] = acc + b_out[0];
}

// ---------------- host launcher ----------------
extern "C" void kernel_launch(void* const* d_in, const int* in_sizes, int n_in,
                              void* d_out, int out_size) {
    const float* vm_states = (const float*)d_in[0];
    const float* num_step  = (const float*)d_in[1];
    const float* pm_states = (const float*)d_in[2];
    const float* W_pm = (const float*)d_in[3];
    const float* b_pm = (const float*)d_in[4];
    const float* W_vm = (const float*)d_in[5];
    const float* b_vm = (const float*)d_in[6];
    const float* critic = (const float*)d_in[7];
    const float* ln1_g = (const float*)d_in[8];
    const float* ln1_b = (const float*)d_in[9];
    const float* Wq = (const float*)d_in[10];
    const float* bq = (const float*)d_in[11];
    const float* Wk = (const float*)d_in[12];
    const float* bk = (const float*)d_in[13];
    const float* Wv = (const float*)d_in[14];
    const float* bv = (const float*)d_in[15];
    const float* Wo = (const float*)d_in[16];
    const float* bo = (const float*)d_in[17];
    const float* ln2_g = (const float*)d_in[18];
    const float* ln2_b = (const float*)d_in[19];
    const float* W1 = (const float*)d_in[20];
    const float* b1 = (const float*)d_in[21];
    const float* W2 = (const float*)d_in[22];
    const float* b2 = (const float*)d_in[23];
    const float* W_out = (const float*)d_in[24];
    const float* b_out = (const float*)d_in[25];
    float* out = (float*)d_out;

    void *ph, *pq, *pk, *pv, *po, *pf, *px;
    void *pWq, *pWk, *pWv, *pWo, *pW1, *pW2;
    cudaGetSymbolAddress(&px, g_x);
    cudaGetSymbolAddress(&ph, g_h);
    cudaGetSymbolAddress(&pq, g_q);
    cudaGetSymbolAddress(&pk, g_k);
    cudaGetSymbolAddress(&pv, g_v);
    cudaGetSymbolAddress(&po, g_o);
    cudaGetSymbolAddress(&pf, g_ffn);
    cudaGetSymbolAddress(&pWq, g_Wqt);
    cudaGetSymbolAddress(&pWk, g_Wkt);
    cudaGetSymbolAddress(&pWv, g_Wvt);
    cudaGetSymbolAddress(&pWo, g_Wot);
    cudaGetSymbolAddress(&pW1, g_W1t);
    cudaGetSymbolAddress(&pW2, g_W2t);
    float* x = (float*)px;
    __half* h = (__half*)ph;
    float* q = (float*)pq;
    float* k = (float*)pk;
    float* v = (float*)pv;
    __half* o = (__half*)po;
    __half* f = (__half*)pf;
    __half* rWq = (__half*)pWq;
    __half* rWk = (__half*)pWk;
    __half* rWv = (__half*)pWv;
    __half* rWo = (__half*)pWo;
    __half* rW1 = (__half*)pW1;
    __half* rW2 = (__half*)pW2;

    cudaFuncSetAttribute(gemm_h, cudaFuncAttributeMaxDynamicSharedMemorySize, GEMM_SMEM_H);

    // all 6 weight transposes in one launch
    transpose_all<<<2304, dim3(32, 8)>>>(Wq, Wk, Wv, Wo, W1, W2);

    embed_kernel<<<dim3(SEQL, BATCH), DMODEL>>>(vm_states, num_step, pm_states,
                                                W_pm, b_pm, W_vm, b_vm, critic);
    build_init<<<(BATCH * NUM_PM + 255) / 256, 256>>>();
    build_vm<<<(BATCH * NUM_VM + 255) / 256, 256>>>(vm_states);

    const int M = MROWS;
    const int gridM = (M + 127) / 128;              // 82
    dim3 gQKV(DMODEL / 128, gridM, 3);              // (2, 82, 3)
    dim3 g256(DMODEL / 128, gridM, 1);              // (2, 82)
    dim3 g1024(DFF / 128, gridM, 1);                // (8, 82)
    dim3 gln((MROWS + 7) / 8);
    dim3 gattn((BATCH * SEQL + 7) / 8);

    for (int l = 0; l < NLAYER; l++) {
        ln_kernel<<<gln, 256>>>(ln1_g + l * DMODEL, ln1_b + l * DMODEL);
        gemm_h<<<gQKV, 128, GEMM_SMEM_H>>>(h,
            rWq + l * DMODEL * DMODEL, rWk + l * DMODEL * DMODEL, rWv + l * DMODEL * DMODEL,
            bq + l * DMODEL, bk + l * DMODEL, bv + l * DMODEL,
            q, k, v, nullptr, M, DMODEL, DMODEL, 0);
        attn_kernel<<<gattn, 256>>>();
        gemm_h<<<g256, 128, GEMM_SMEM_H>>>(o,
            rWo + l * DMODEL * DMODEL, rWo + l * DMODEL * DMODEL, rWo + l * DMODEL * DMODEL,
            bo + l * DMODEL, bo + l * DMODEL, bo + l * DMODEL,
            x, x, x, x, M, DMODEL, DMODEL, 0);
        ln_kernel<<<gln, 256>>>(ln2_g + l * DMODEL, ln2_b + l * DMODEL);
        gemm_h<<<g1024, 128, GEMM_SMEM_H>>>(h,
            rW1 + l * DMODEL * DFF, rW1 + l * DMODEL * DFF, rW1 + l * DMODEL * DFF,
            b1 + l * DFF, b1 + l * DFF, b1 + l * DFF,
            f, f, f, nullptr, M, DFF, DMODEL, 1);
        gemm_h<<<g256, 128, GEMM_SMEM_H>>>(f,
            rW2 + l * DFF * DMODEL, rW2 + l * DFF * DMODEL, rW2 + l * DFF * DMODEL,
            b2 + l * DMODEL, b2 + l * DMODEL, b2 + l * DMODEL,
            x, x, x, x, M, DMODEL, DFF, 0);
    }

    out_kernel<<<dim3((NUM_VM + 7) / 8, BATCH), 256>>>(W_out, b_out, out);
}

// round 12
// speedup vs baseline: 1.3651x; 1.3651x over previous
#include <cuda_runtime.h>
#include <cuda_fp16.h>
#include <cstdint>

#define BATCH 8
#define NUM_PM 300
#define NUM_VM 1000
#define PM_COV 8
#define DMODEL 256
#define NHEAD 8
#define DHEAD 32
#define DFF 1024
#define NLAYER 3
#define SEQL (NUM_PM + NUM_VM + 2)   // 1302
#define MROWS (BATCH * SEQL)          // 10416
#define CAP 64

// ---------------- static scratch ----------------
__device__ float  g_x[MROWS * DMODEL];
__device__ __half g_h[MROWS * DMODEL];
__device__ float  g_q[MROWS * DMODEL];
__device__ float  g_k[MROWS * DMODEL];
__device__ float  g_v[MROWS * DMODEL];
__device__ __half g_o[MROWS * DMODEL];
__device__ __half g_ffn[MROWS * DFF];
__device__ int    g_rel[MROWS];
__device__ int    g_cnt[BATCH * NUM_PM];
__device__ int    g_list[BATCH * NUM_PM * CAP];
// transposed + fp16 weights, [N][K] K-major
__device__ __half g_Wqt[NLAYER * DMODEL * DMODEL];
__device__ __half g_Wkt[NLAYER * DMODEL * DMODEL];
__device__ __half g_Wvt[NLAYER * DMODEL * DMODEL];
__device__ __half g_Wot[NLAYER * DMODEL * DMODEL];
__device__ __half g_W1t[NLAYER * DMODEL * DFF];
__device__ __half g_W2t[NLAYER * DFF * DMODEL];

__device__ __forceinline__ uint32_t h2_u32(__half2 h) {
    union { __half2 h2; uint32_t u; } cv;
    cv.h2 = h;
    return cv.u;
}

// ---------------- embed + rel ----------------
__global__ void embed_kernel(const float* __restrict__ vm_states,
                             const float* __restrict__ num_step,
                             const float* __restrict__ pm_states,
                             const float* __restrict__ W_pm, const float* __restrict__ b_pm,
                             const float* __restrict__ W_vm, const float* __restrict__ b_vm,
                             const float* __restrict__ critic) {
    int b = blockIdx.y;
    int l = blockIdx.x;
    int d = threadIdx.x;
    float val;
    if (l == 0) {
        val = num_step[b];
    } else if (l <= NUM_PM) {
        const float* pm = pm_states + (b * NUM_PM + (l - 1)) * PM_COV;
        float acc = b_pm[d];
        #pragma unroll
        for (int c = 0; c < PM_COV; c++) acc += pm[c] * W_pm[c * DMODEL + d];
        val = acc;
    } else if (l <= NUM_PM + NUM_VM) {
        const float* vm = vm_states + (b * NUM_VM + (l - 1 - NUM_PM)) * 7;
        float acc = b_vm[d];
        #pragma unroll
        for (int c = 0; c < 6; c++) acc += vm[c] * W_vm[c * DMODEL + d];
        val = acc;
    } else {
        val = critic[d];
    }
    g_x[(b * SEQL + l) * DMODEL + d] = val;
    if (d == 0) {
        int r = -100;
        if (l >= 1 && l <= NUM_PM) r = l - 1;
        else if (l > NUM_PM && l < SEQL - 1)
            r = (int)vm_states[(b * NUM_VM + (l - 1 - NUM_PM)) * 7 + 6];
        g_rel[b * SEQL + l] = r;
    }
}

// ---------------- group list build ----------------
__global__ void build_init() {
    int i = blockIdx.x * 256 + threadIdx.x;
    if (i >= BATCH * NUM_PM) return;
    int r = i % NUM_PM;
    g_cnt[i] = 1;
    g_list[i * CAP] = 1 + r;
}

__global__ void build_vm(const float* __restrict__ vm_states) {
    int i = blockIdx.x * 256 + threadIdx.x;
    if (i >= BATCH * NUM_VM) return;
    int b = i / NUM_VM, j = i % NUM_VM;
    int r = (int)vm_states[(b * NUM_VM + j) * 7 + 6];
    int p = atomicAdd(&g_cnt[b * NUM_PM + r], 1);
    if (p < CAP) g_list[(b * NUM_PM + r) * CAP + p] = NUM_PM + 1 + j;
}

// ---------------- fused weight transpose + fp16: all 6 weights, one launch ----------------
__global__ void transpose_all(const float* __restrict__ Wq, const float* __restrict__ Wk,
                              const float* __restrict__ Wv, const float* __restrict__ Wo,
                              const float* __restrict__ W1, const float* __restrict__ W2) {
    __shared__ float t[32][33];
    int bid = blockIdx.x;
    const float* src;
    __half* dst;
    int K, N, ti;
    if (bid < 768) {
        int w = bid / 192;
        ti = bid % 192;
        src = (w == 0) ? Wq : (w == 1) ? Wk : (w == 2) ? Wv : Wo;
        dst = (w == 0) ? g_Wqt : (w == 1) ? g_Wkt : (w == 2) ? g_Wvt : g_Wot;
        K = DMODEL; N = DMODEL;
    } else if (bid < 1536) {
        ti = bid - 768; src = W1; dst = g_W1t; K = DMODEL; N = DFF;
    } else {
        ti = bid - 1536; src = W2; dst = g_W2t; K = DFF; N = DMODEL;
    }
    int tilesN = N >> 5;
    int perLayer = (K >> 5) * tilesN;
    int layer = ti / perLayer;
    int tt = ti - layer * perLayer;
    int k0 = (tt / tilesN) << 5, n0 = (tt % tilesN) << 5;
    const float* s = src + layer * K * N;
    __half* d = dst + layer * K * N;
    int tx = threadIdx.x, ty = threadIdx.y;
    #pragma unroll
    for (int j = 0; j < 32; j += 8)
        t[ty + j][tx] = s[(k0 + ty + j) * N + n0 + tx];
    __syncthreads();
    #pragma unroll
    for (int j = 0; j < 32; j += 8)
        d[(n0 + ty + j) * K + k0 + tx] = __float2half(t[tx][ty + j]);
}

// ---------------- layernorm: warp per row, fp16 output ----------------
__global__ void ln_kernel(const float* __restrict__ gamma, const float* __restrict__ beta) {
    int row = blockIdx.x * 8 + (threadIdx.x >> 5);
    if (row >= MROWS) return;
    int lane = threadIdx.x & 31;
    const float4* xr = (const float4*)(g_x + row * DMODEL) + lane * 2;
    float4 a = xr[0], c4 = xr[1];
    float v8[8] = {a.x, a.y, a.z, a.w, c4.x, c4.y, c4.z, c4.w};
    float s = 0.f;
    #pragma unroll
    for (int t = 0; t < 8; t++) s += v8[t];
    #pragma unroll
    for (int o = 16; o > 0; o >>= 1) s += __shfl_xor_sync(0xffffffffu, s, o);
    float mean = s * (1.0f / DMODEL);
    float vs = 0.f;
    #pragma unroll
    for (int t = 0; t < 8; t++) { v8[t] -= mean; vs += v8[t] * v8[t]; }
    #pragma unroll
    for (int o = 16; o > 0; o >>= 1) vs += __shfl_xor_sync(0xffffffffu, vs, o);
    float r = rsqrtf(vs * (1.0f / DMODEL) + 1e-5f);
    const float4* gg = (const float4*)gamma + lane * 2;
    const float4* bb = (const float4*)beta + lane * 2;
    float4 g0 = gg[0], g1 = gg[1], b0 = bb[0], b1 = bb[1];
    float ge[8] = {g0.x, g0.y, g0.z, g0.w, g1.x, g1.y, g1.z, g1.w};
    float be[8] = {b0.x, b0.y, b0.z, b0.w, b1.x, b1.y, b1.z, b1.w};
    uint4 pack;
    pack.x = h2_u32(__floats2half2_rn(v8[0] * r * ge[0] + be[0], v8[1] * r * ge[1] + be[1]));
    pack.y = h2_u32(__floats2half2_rn(v8[2] * r * ge[2] + be[2], v8[3] * r * ge[3] + be[3]));
    pack.z = h2_u32(__floats2half2_rn(v8[4] * r * ge[4] + be[4], v8[5] * r * ge[5] + be[5]));
    pack.w = h2_u32(__floats2half2_rn(v8[6] * r * ge[6] + be[6], v8[7] * r * ge[7] + be[7]));
    *((uint4*)(g_h + row * DMODEL) + lane) = pack;
}

// ---------------- GELU (tanh approx) ----------------
__device__ __forceinline__ float gelu_f(float x) {
    float x3 = x * x * x;
    float t = tanhf(0.7978845608028654f * (x + 0.044715f * x3));
    return 0.5f * x * (1.0f + t);
}

// ================= fp16 mma.sync GEMM =================
// CTA tile 128x64, 8 warps (4x2), warp tile 32x32, BK=64 halfs,
// 2-stage double buffer (R8-proven two-barrier scheme), 3 CTAs/SM.
#define BKh 64
#define HSTRIDE 72
#define A_STAGE_H (128 * HSTRIDE)              // 9216 halfs (A: 128 rows)
#define B_STAGE_H (64 * HSTRIDE)               // 4608 halfs (B: 64 rows)
#define STAGE_H   (A_STAGE_H + B_STAGE_H)      // 13824 halfs = 27648 B
#define NSTAGE 2
#define GEMM_SMEM_H (NSTAGE * STAGE_H * 2)     // 55296 bytes -> 3 CTAs/SM

__device__ __forceinline__ void cp16s(uint32_t saddr, const void* g) {
    asm volatile("cp.async.cg.shared.global [%0], [%1], 16;\n" :: "r"(saddr), "l"(g));
}
#define CP_COMMIT() asm volatile("cp.async.commit_group;\n" ::: "memory")
#define CP_WAIT(n)  asm volatile("cp.async.wait_group %0;\n" :: "n"(n) : "memory")
__device__ __forceinline__ uint32_t smem_u32(const void* p) {
    uint32_t a;
    asm("{ .reg .u64 t; cvta.to.shared.u64 t, %1; cvt.u32.u64 %0, t; }" : "=r"(a) : "l"(p));
    return a;
}

// z-dim selects among up to 3 weight/bias/output sets (QKV fusion).
__global__ void __launch_bounds__(256, 3)
gemm_h(const __half* __restrict__ A,
       const __half* __restrict__ Wt0, const __half* __restrict__ Wt1,
       const __half* __restrict__ Wt2,
       const float* __restrict__ bias0, const float* __restrict__ bias1,
       const float* __restrict__ bias2,
       void* __restrict__ C0, void* __restrict__ C1, void* __restrict__ C2,
       const float* __restrict__ res,
       int M, int N, int K, int act) {
    const __half* Wt  = (blockIdx.z == 0) ? Wt0   : (blockIdx.z == 1) ? Wt1   : Wt2;
    const float* bias = (blockIdx.z == 0) ? bias0 : (blockIdx.z == 1) ? bias1 : bias2;
    void* Cv          = (blockIdx.z == 0) ? C0    : (blockIdx.z == 1) ? C1    : C2;

    extern __shared__ __half smh[];
    const int tid = threadIdx.x;
    const int m0 = blockIdx.y * 128;
    const int n0 = blockIdx.x * 64;
    const int lane = tid & 31;
    const int warp = tid >> 5;
    const int wm = warp >> 1;          // 0..3
    const int wn = warp & 1;           // 0..1
    const int lq = lane >> 2;          // 0..7
    const int lr = lane & 3;           // 0..3

    float c[2][4][4];
    #pragma unroll
    for (int i = 0; i < 2; i++)
        #pragma unroll
        for (int j = 0; j < 4; j++)
            #pragma unroll
            for (int p = 0; p < 4; p++) c[i][j][p] = 0.f;

    uint32_t sb = smem_u32(smh);

    auto loadStage = [&](int stage, int ct) {
        int kc = ct * BKh;
        uint32_t offA = sb + stage * (STAGE_H * 2);
        uint32_t offB = offA + A_STAGE_H * 2;
        #pragma unroll
        for (int p = 0; p < 4; p++) {       // A: 128 rows x 8 segs = 1024 cp16
            int i = tid + p * 256;
            int r = i >> 3, seg = i & 7;
            int gm = m0 + r;
            if (gm >= M) gm = M - 1;
            cp16s(offA + (r * HSTRIDE + seg * 8) * 2, A + gm * K + kc + seg * 8);
        }
        #pragma unroll
        for (int p = 0; p < 2; p++) {       // B: 64 rows x 8 segs = 512 cp16
            int i = tid + p * 256;
            int r = i >> 3, seg = i & 7;
            cp16s(offB + (r * HSTRIDE + seg * 8) * 2, Wt + (n0 + r) * K + kc + seg * 8);
        }
    };

    auto computeStage = [&](int stage) {
        const __half* As = smh + stage * STAGE_H;
        const __half* Bs = As + A_STAGE_H;
        #pragma unroll
        for (int kk = 0; kk < BKh; kk += 16) {
            uint32_t af[2][4], bf[4][2];
            #pragma unroll
            for (int tm = 0; tm < 2; tm++) {
                const __half* ap = As + (wm * 32 + tm * 16 + lq) * HSTRIDE + kk + 2 * lr;
                af[tm][0] = *(const uint32_t*)(ap);
                af[tm][1] = *(const uint32_t*)(ap + 8 * HSTRIDE);
                af[tm][2] = *(const uint32_t*)(ap + 8);
                af[tm][3] = *(const uint32_t*)(ap + 8 * HSTRIDE + 8);
            }
            #pragma unroll
            for (int tn = 0; tn < 4; tn++) {
                const __half* bp = Bs + (wn * 32 + tn * 8 + lq) * HSTRIDE + kk + 2 * lr;
                bf[tn][0] = *(const uint32_t*)(bp);
                bf[tn][1] = *(const uint32_t*)(bp + 8);
            }
            #pragma unroll
            for (int tm = 0; tm < 2; tm++)
                #pragma unroll
                for (int tn = 0; tn < 4; tn++) {
                    asm volatile(
                        "mma.sync.aligned.m16n8k16.row.col.f32.f16.f16.f32 "
                        "{%0,%1,%2,%3}, {%4,%5,%6,%7}, {%8,%9}, {%0,%1,%2,%3};\n"
                        : "+f"(c[tm][tn][0]), "+f"(c[tm][tn][1]),
                          "+f"(c[tm][tn][2]), "+f"(c[tm][tn][3])
                        : "r"(af[tm][0]), "r"(af[tm][1]), "r"(af[tm][2]), "r"(af[tm][3]),
                          "r"(bf[tn][0]), "r"(bf[tn][1]));
                }
        }
    };

    const int KT = K / BKh;
    // R8-proven two-barrier double buffer.
    loadStage(0, 0);
    CP_COMMIT();
    int buf = 0;
    for (int ct = 0; ct < KT; ct++) {
        if (ct + 1 < KT) {
            loadStage(buf ^ 1, ct + 1);
            CP_COMMIT();
            CP_WAIT(1);
        } else {
            CP_WAIT(0);
        }
        __syncthreads();
        computeStage(buf);
        __syncthreads();
        buf ^= 1;
    }

    // epilogue
    #pragma unroll
    for (int tm = 0; tm < 2; tm++) {
        #pragma unroll
        for (int tn = 0; tn < 4; tn++) {
            int row0 = m0 + wm * 32 + tm * 16 + lq;
            int col = n0 + wn * 32 + tn * 8 + 2 * lr;
            #pragma unroll
            for (int half_i = 0; half_i < 2; half_i++) {
                int r = row0 + half_i * 8;
                if (r < M) {
                    float v0 = c[tm][tn][half_i * 2 + 0] + bias[col];
                    float v1 = c[tm][tn][half_i * 2 + 1] + bias[col + 1];
                    if (res) { v0 += res[r * N + col]; v1 += res[r * N + col + 1]; }
                    if (act) {
                        __half2 hv = __floats2half2_rn(gelu_f(v0), gelu_f(v1));
                        *(__half2*)((__half*)Cv + r * N + col) = hv;
                    } else {
                        float* C = (float*)Cv;
                        C[r * N + col] = v0;
                        C[r * N + col + 1] = v1;
                    }
                }
            }
        }
    }
}

// ---------------- sparse attention: warp per (b, query), fp16 output ----------------
__global__ void attn_kernel() {
    int gw = blockIdx.x * 8 + (threadIdx.x >> 5);
    if (gw >= BATCH * SEQL) return;
    int b = gw / SEQL;
    int l = gw - b * SEQL;
    int lane = threadIdx.x & 31;
    int row = b * SEQL + l;

    if (l == 0 || l == SEQL - 1) {
        #pragma unroll
        for (int t = 0; t < 8; t++)
            g_o[row * DMODEL + lane + 32 * t] = __float2half(g_v[row * DMODEL + lane + 32 * t]);
        return;
    }

    int r = g_rel[row];
    int cnt = g_cnt[b * NUM_PM + r];
    if (cnt > CAP) cnt = CAP;
    const int* lst = g_list + (b * NUM_PM + r) * CAP;

    const float scale = 0.17677669529663687f;
    float q8[8], o8[8], mx[8], sum[8];
    #pragma unroll
    for (int h = 0; h < 8; h++) {
        q8[h] = g_q[row * DMODEL + lane + 32 * h] * scale;
        o8[h] = 0.f; mx[h] = -1e30f; sum[h] = 0.f;
    }

    for (int i = 0; i < cnt; i++) {
        int krow = b * SEQL + lst[i];
        float k8[8], v8[8];
        #pragma unroll
        for (int t = 0; t < 8; t++) {
            k8[t] = g_k[krow * DMODEL + lane + 32 * t];
            v8[t] = g_v[krow * DMODEL + lane + 32 * t];
        }
        #pragma unroll
        for (int h = 0; h < 8; h++) {
            float d = q8[h] * k8[h];
            #pragma unroll
            for (int o = 16; o > 0; o >>= 1) d += __shfl_xor_sync(0xffffffffu, d, o);
            float nm = fmaxf(mx[h], d);
            float corr = __expf(mx[h] - nm);
            float p = __expf(d - nm);
            sum[h] = sum[h] * corr + p;
            o8[h] = o8[h] * corr + p * v8[h];
            mx[h] = nm;
        }
    }
    #pragma unroll
    for (int h = 0; h < 8; h++)
        g_o[row * DMODEL + lane + 32 * h] = __float2half(o8[h] / sum[h]);
}

// ---------------- output head ----------------
__global__ void out_kernel(const float* __restrict__ W_out, const float* __restrict__ b_out,
                           float* __restrict__ out) {
    int b = blockIdx.y;
    int warp = threadIdx.x >> 5;
    int lane = threadIdx.x & 31;
    int j = blockIdx.x * 8 + warp;
    if (j >= NUM_VM) return;
    int row = b * SEQL + NUM_PM + 1 + j;
    float acc = 0.f;
    #pragma unroll
    for (int d = lane; d < DMODEL; d += 32)
        acc += g_x[row * DMODEL + d] * W_out[d];
    #pragma unroll
    for (int o = 16; o > 0; o >>= 1) acc += __shfl_xor_sync(0xffffffffu, acc, o);
    if (lane == 0) out[b * NUM_VM + j] = acc + b_out[0];
}

// ---------------- host launcher ----------------
extern "C" void kernel_launch(void* const* d_in, const int* in_sizes, int n_in,
                              void* d_out, int out_size) {
    const float* vm_states = (const float*)d_in[0];
    const float* num_step  = (const float*)d_in[1];
    const float* pm_states = (const float*)d_in[2];
    const float* W_pm = (const float*)d_in[3];
    const float* b_pm = (const float*)d_in[4];
    const float* W_vm = (const float*)d_in[5];
    const float* b_vm = (const float*)d_in[6];
    const float* critic = (const float*)d_in[7];
    const float* ln1_g = (const float*)d_in[8];
    const float* ln1_b = (const float*)d_in[9];
    const float* Wq = (const float*)d_in[10];
    const float* bq = (const float*)d_in[11];
    const float* Wk = (const float*)d_in[12];
    const float* bk = (const float*)d_in[13];
    const float* Wv = (const float*)d_in[14];
    const float* bv = (const float*)d_in[15];
    const float* Wo = (const float*)d_in[16];
    const float* bo = (const float*)d_in[17];
    const float* ln2_g = (const float*)d_in[18];
    const float* ln2_b = (const float*)d_in[19];
    const float* W1 = (const float*)d_in[20];
    const float* b1 = (const float*)d_in[21];
    const float* W2 = (const float*)d_in[22];
    const float* b2 = (const float*)d_in[23];
    const float* W_out = (const float*)d_in[24];
    const float* b_out = (const float*)d_in[25];
    float* out = (float*)d_out;

    void *ph, *pq, *pk, *pv, *po, *pf, *px;
    void *pWq, *pWk, *pWv, *pWo, *pW1, *pW2;
    cudaGetSymbolAddress(&px, g_x);
    cudaGetSymbolAddress(&ph, g_h);
    cudaGetSymbolAddress(&pq, g_q);
    cudaGetSymbolAddress(&pk, g_k);
    cudaGetSymbolAddress(&pv, g_v);
    cudaGetSymbolAddress(&po, g_o);
    cudaGetSymbolAddress(&pf, g_ffn);
    cudaGetSymbolAddress(&pWq, g_Wqt);
    cudaGetSymbolAddress(&pWk, g_Wkt);
    cudaGetSymbolAddress(&pWv, g_Wvt);
    cudaGetSymbolAddress(&pWo, g_Wot);
    cudaGetSymbolAddress(&pW1, g_W1t);
    cudaGetSymbolAddress(&pW2, g_W2t);
    float* x = (float*)px;
    __half* h = (__half*)ph;
    float* q = (float*)pq;
    float* k = (float*)pk;
    float* v = (float*)pv;
    __half* o = (__half*)po;
    __half* f = (__half*)pf;
    __half* rWq = (__half*)pWq;
    __half* rWk = (__half*)pWk;
    __half* rWv = (__half*)pWv;
    __half* rWo = (__half*)pWo;
    __half* rW1 = (__half*)pW1;
    __half* rW2 = (__half*)pW2;

    cudaFuncSetAttribute(gemm_h, cudaFuncAttributeMaxDynamicSharedMemorySize, GEMM_SMEM_H);

    // all 6 weight transposes in one launch
    transpose_all<<<2304, dim3(32, 8)>>>(Wq, Wk, Wv, Wo, W1, W2);

    embed_kernel<<<dim3(SEQL, BATCH), DMODEL>>>(vm_states, num_step, pm_states,
                                                W_pm, b_pm, W_vm, b_vm, critic);
    build_init<<<(BATCH * NUM_PM + 255) / 256, 256>>>();
    build_vm<<<(BATCH * NUM_VM + 255) / 256, 256>>>(vm_states);

    const int M = MROWS;
    const int gridM = (M + 127) / 128;              // 82
    dim3 gQKV(DMODEL / 64, gridM, 3);               // (4, 82, 3)
    dim3 g256(DMODEL / 64, gridM, 1);               // (4, 82)
    dim3 g1024(DFF / 64, gridM, 1);                 // (16, 82)
    dim3 gln((MROWS + 7) / 8);
    dim3 gattn((BATCH * SEQL + 7) / 8);

    for (int l = 0; l < NLAYER; l++) {
        ln_kernel<<<gln, 256>>>(ln1_g + l * DMODEL, ln1_b + l * DMODEL);
        gemm_h<<<gQKV, 256, GEMM_SMEM_H>>>(h,
            rWq + l * DMODEL * DMODEL, rWk + l * DMODEL * DMODEL, rWv + l * DMODEL * DMODEL,
            bq + l * DMODEL, bk + l * DMODEL, bv + l * DMODEL,
            q, k, v, nullptr, M, DMODEL, DMODEL, 0);
        attn_kernel<<<gattn, 256>>>();
        gemm_h<<<g256, 256, GEMM_SMEM_H>>>(o,
            rWo + l * DMODEL * DMODEL, rWo + l * DMODEL * DMODEL, rWo + l * DMODEL * DMODEL,
            bo + l * DMODEL, bo + l * DMODEL, bo + l * DMODEL,
            x, x, x, x, M, DMODEL, DMODEL, 0);
        ln_kernel<<<gln, 256>>>(ln2_g + l * DMODEL, ln2_b + l * DMODEL);
        gemm_h<<<g1024, 256, GEMM_SMEM_H>>>(h,
            rW1 + l * DMODEL * DFF, rW1 + l * DMODEL * DFF, rW1 + l * DMODEL * DFF,
            b1 + l * DFF, b1 + l * DFF, b1 + l * DFF,
            f, f, f, nullptr, M, DFF, DMODEL, 1);
        gemm_h<<<g256, 256, GEMM_SMEM_H>>>(f,
            rW2 + l * DFF * DMODEL, rW2 + l * DFF * DMODEL, rW2 + l * DFF * DMODEL,
            b2 + l * DMODEL, b2 + l * DMODEL, b2 + l * DMODEL,
            x, x, x, x, M, DMODEL, DFF, 0);
    }

    out_kernel<<<dim3((NUM_VM + 7) / 8, BATCH), 256>>>(W_out, b_out, out);
}

// round 14
// speedup vs baseline: 1.4426x; 1.0568x over previous
#include <cuda_runtime.h>
#include <cuda_fp16.h>
#include <cstdint>

#define BATCH 8
#define NUM_PM 300
#define NUM_VM 1000
#define PM_COV 8
#define DMODEL 256
#define NHEAD 8
#define DHEAD 32
#define DFF 1024
#define NLAYER 3
#define SEQL (NUM_PM + NUM_VM + 2)   // 1302
#define MROWS (BATCH * SEQL)          // 10416
#define CAP 64

// ---------------- static scratch ----------------
__device__ float  g_x[MROWS * DMODEL];
__device__ __half g_h[MROWS * DMODEL];
__device__ float  g_q[MROWS * DMODEL];
__device__ float  g_k[MROWS * DMODEL];
__device__ float  g_v[MROWS * DMODEL];
__device__ __half g_o[MROWS * DMODEL];
__device__ __half g_ffn[MROWS * DFF];
__device__ int    g_rel[MROWS];
__device__ int    g_cnt[BATCH * NUM_PM];
__device__ int    g_list[BATCH * NUM_PM * CAP];
// transposed + fp16 weights, [N][K] K-major
__device__ __half g_Wqt[NLAYER * DMODEL * DMODEL];
__device__ __half g_Wkt[NLAYER * DMODEL * DMODEL];
__device__ __half g_Wvt[NLAYER * DMODEL * DMODEL];
__device__ __half g_Wot[NLAYER * DMODEL * DMODEL];
__device__ __half g_W1t[NLAYER * DMODEL * DFF];
__device__ __half g_W2t[NLAYER * DFF * DMODEL];

__device__ __forceinline__ uint32_t h2_u32(__half2 h) {
    union { __half2 h2; uint32_t u; } cv;
    cv.h2 = h;
    return cv.u;
}

// ---------------- embed + rel ----------------
__global__ void embed_kernel(const float* __restrict__ vm_states,
                             const float* __restrict__ num_step,
                             const float* __restrict__ pm_states,
                             const float* __restrict__ W_pm, const float* __restrict__ b_pm,
                             const float* __restrict__ W_vm, const float* __restrict__ b_vm,
                             const float* __restrict__ critic) {
    int b = blockIdx.y;
    int l = blockIdx.x;
    int d = threadIdx.x;
    float val;
    if (l == 0) {
        val = num_step[b];
    } else if (l <= NUM_PM) {
        const float* pm = pm_states + (b * NUM_PM + (l - 1)) * PM_COV;
        float acc = b_pm[d];
        #pragma unroll
        for (int c = 0; c < PM_COV; c++) acc += pm[c] * W_pm[c * DMODEL + d];
        val = acc;
    } else if (l <= NUM_PM + NUM_VM) {
        const float* vm = vm_states + (b * NUM_VM + (l - 1 - NUM_PM)) * 7;
        float acc = b_vm[d];
        #pragma unroll
        for (int c = 0; c < 6; c++) acc += vm[c] * W_vm[c * DMODEL + d];
        val = acc;
    } else {
        val = critic[d];
    }
    g_x[(b * SEQL + l) * DMODEL + d] = val;
    if (d == 0) {
        int r = -100;
        if (l >= 1 && l <= NUM_PM) r = l - 1;
        else if (l > NUM_PM && l < SEQL - 1)
            r = (int)vm_states[(b * NUM_VM + (l - 1 - NUM_PM)) * 7 + 6];
        g_rel[b * SEQL + l] = r;
    }
}

// ---------------- group list build ----------------
__global__ void build_init() {
    int i = blockIdx.x * 256 + threadIdx.x;
    if (i >= BATCH * NUM_PM) return;
    int r = i % NUM_PM;
    g_cnt[i] = 1;
    g_list[i * CAP] = 1 + r;
}

__global__ void build_vm(const float* __restrict__ vm_states) {
    int i = blockIdx.x * 256 + threadIdx.x;
    if (i >= BATCH * NUM_VM) return;
    int b = i / NUM_VM, j = i % NUM_VM;
    int r = (int)vm_states[(b * NUM_VM + j) * 7 + 6];
    int p = atomicAdd(&g_cnt[b * NUM_PM + r], 1);
    if (p < CAP) g_list[(b * NUM_PM + r) * CAP + p] = NUM_PM + 1 + j;
}

// ---------------- fused weight transpose + fp16: all 6 weights, one launch ----------------
__global__ void transpose_all(const float* __restrict__ Wq, const float* __restrict__ Wk,
                              const float* __restrict__ Wv, const float* __restrict__ Wo,
                              const float* __restrict__ W1, const float* __restrict__ W2) {
    __shared__ float t[32][33];
    int bid = blockIdx.x;
    const float* src;
    __half* dst;
    int K, N, ti;
    if (bid < 768) {
        int w = bid / 192;
        ti = bid % 192;
        src = (w == 0) ? Wq : (w == 1) ? Wk : (w == 2) ? Wv : Wo;
        dst = (w == 0) ? g_Wqt : (w == 1) ? g_Wkt : (w == 2) ? g_Wvt : g_Wot;
        K = DMODEL; N = DMODEL;
    } else if (bid < 1536) {
        ti = bid - 768; src = W1; dst = g_W1t; K = DMODEL; N = DFF;
    } else {
        ti = bid - 1536; src = W2; dst = g_W2t; K = DFF; N = DMODEL;
    }
    int tilesN = N >> 5;
    int perLayer = (K >> 5) * tilesN;
    int layer = ti / perLayer;
    int tt = ti - layer * perLayer;
    int k0 = (tt / tilesN) << 5, n0 = (tt % tilesN) << 5;
    const float* s = src + layer * K * N;
    __half* d = dst + layer * K * N;
    int tx = threadIdx.x, ty = threadIdx.y;
    #pragma unroll
    for (int j = 0; j < 32; j += 8)
        t[ty + j][tx] = s[(k0 + ty + j) * N + n0 + tx];
    __syncthreads();
    #pragma unroll
    for (int j = 0; j < 32; j += 8)
        d[(n0 + ty + j) * K + k0 + tx] = __float2half(t[tx][ty + j]);
}

// ---------------- layernorm: warp per row, fp16 output ----------------
__global__ void ln_kernel(const float* __restrict__ gamma, const float* __restrict__ beta) {
    int row = blockIdx.x * 8 + (threadIdx.x >> 5);
    if (row >= MROWS) return;
    int lane = threadIdx.x & 31;
    const float4* xr = (const float4*)(g_x + row * DMODEL) + lane * 2;
    float4 a = xr[0], c4 = xr[1];
    float v8[8] = {a.x, a.y, a.z, a.w, c4.x, c4.y, c4.z, c4.w};
    float s = 0.f;
    #pragma unroll
    for (int t = 0; t < 8; t++) s += v8[t];
    #pragma unroll
    for (int o = 16; o > 0; o >>= 1) s += __shfl_xor_sync(0xffffffffu, s, o);
    float mean = s * (1.0f / DMODEL);
    float vs = 0.f;
    #pragma unroll
    for (int t = 0; t < 8; t++) { v8[t] -= mean; vs += v8[t] * v8[t]; }
    #pragma unroll
    for (int o = 16; o > 0; o >>= 1) vs += __shfl_xor_sync(0xffffffffu, vs, o);
    float r = rsqrtf(vs * (1.0f / DMODEL) + 1e-5f);
    const float4* gg = (const float4*)gamma + lane * 2;
    const float4* bb = (const float4*)beta + lane * 2;
    float4 g0 = gg[0], g1 = gg[1], b0 = bb[0], b1 = bb[1];
    float ge[8] = {g0.x, g0.y, g0.z, g0.w, g1.x, g1.y, g1.z, g1.w};
    float be[8] = {b0.x, b0.y, b0.z, b0.w, b1.x, b1.y, b1.z, b1.w};
    uint4 pack;
    pack.x = h2_u32(__floats2half2_rn(v8[0] * r * ge[0] + be[0], v8[1] * r * ge[1] + be[1]));
    pack.y = h2_u32(__floats2half2_rn(v8[2] * r * ge[2] + be[2], v8[3] * r * ge[3] + be[3]));
    pack.z = h2_u32(__floats2half2_rn(v8[4] * r * ge[4] + be[4], v8[5] * r * ge[5] + be[5]));
    pack.w = h2_u32(__floats2half2_rn(v8[6] * r * ge[6] + be[6], v8[7] * r * ge[7] + be[7]));
    *((uint4*)(g_h + row * DMODEL) + lane) = pack;
}

// ---------------- GELU (tanh approx) ----------------
__device__ __forceinline__ float gelu_f(float x) {
    float x3 = x * x * x;
    float t = tanhf(0.7978845608028654f * (x + 0.044715f * x3));
    return 0.5f * x * (1.0f + t);
}

// ================= fp16 mma.sync GEMM =================
// CTA tile 128x64, 8 warps (4x2), warp tile 32x32, BK=64 halfs,
// 2-stage double buffer, 3 CTAs/SM, ldmatrix fragment loads.
#define BKh 64
#define HSTRIDE 72
#define A_STAGE_H (128 * HSTRIDE)              // 9216 halfs (A: 128 rows)
#define B_STAGE_H (64 * HSTRIDE)               // 4608 halfs (B: 64 rows)
#define STAGE_H   (A_STAGE_H + B_STAGE_H)      // 13824 halfs = 27648 B
#define NSTAGE 2
#define GEMM_SMEM_H (NSTAGE * STAGE_H * 2)     // 55296 bytes -> 3 CTAs/SM

__device__ __forceinline__ void cp16s(uint32_t saddr, const void* g) {
    asm volatile("cp.async.cg.shared.global [%0], [%1], 16;\n" :: "r"(saddr), "l"(g));
}
#define CP_COMMIT() asm volatile("cp.async.commit_group;\n" ::: "memory")
#define CP_WAIT(n)  asm volatile("cp.async.wait_group %0;\n" :: "n"(n) : "memory")
__device__ __forceinline__ uint32_t smem_u32(const void* p) {
    uint32_t a;
    asm("{ .reg .u64 t; cvta.to.shared.u64 t, %1; cvt.u32.u64 %0, t; }" : "=r"(a) : "l"(p));
    return a;
}
__device__ __forceinline__ void ldsm4(uint32_t& r0, uint32_t& r1, uint32_t& r2, uint32_t& r3,
                                      uint32_t addr) {
    asm volatile("ldmatrix.sync.aligned.m8n8.x4.shared.b16 {%0,%1,%2,%3}, [%4];"
                 : "=r"(r0), "=r"(r1), "=r"(r2), "=r"(r3) : "r"(addr));
}

// z-dim selects among up to 3 weight/bias/output sets (QKV fusion).
__global__ void __launch_bounds__(256, 3)
gemm_h(const __half* __restrict__ A,
       const __half* __restrict__ Wt0, const __half* __restrict__ Wt1,
       const __half* __restrict__ Wt2,
       const float* __restrict__ bias0, const float* __restrict__ bias1,
       const float* __restrict__ bias2,
       void* __restrict__ C0, void* __restrict__ C1, void* __restrict__ C2,
       const float* __restrict__ res,
       int M, int N, int K, int act) {
    const __half* Wt  = (blockIdx.z == 0) ? Wt0   : (blockIdx.z == 1) ? Wt1   : Wt2;
    const float* bias = (blockIdx.z == 0) ? bias0 : (blockIdx.z == 1) ? bias1 : bias2;
    void* Cv          = (blockIdx.z == 0) ? C0    : (blockIdx.z == 1) ? C1    : C2;

    extern __shared__ __half smh[];
    const int tid = threadIdx.x;
    const int m0 = blockIdx.y * 128;
    const int n0 = blockIdx.x * 64;
    const int lane = tid & 31;
    const int warp = tid >> 5;
    const int wm = warp >> 1;          // 0..3
    const int wn = warp & 1;           // 0..1
    const int lq = lane >> 2;          // 0..7
    const int lr = lane & 3;           // 0..3

    float c[2][4][4];
    #pragma unroll
    for (int i = 0; i < 2; i++)
        #pragma unroll
        for (int j = 0; j < 4; j++)
            #pragma unroll
            for (int p = 0; p < 4; p++) c[i][j][p] = 0.f;

    uint32_t sb = smem_u32(smh);

    auto loadStage = [&](int stage, int ct) {
        int kc = ct * BKh;
        uint32_t offA = sb + stage * (STAGE_H * 2);
        uint32_t offB = offA + A_STAGE_H * 2;
        #pragma unroll
        for (int p = 0; p < 4; p++) {       // A: 128 rows x 8 segs
            int i = tid + p * 256;
            int r = i >> 3, seg = i & 7;
            int gm = m0 + r;
            if (gm >= M) gm = M - 1;
            cp16s(offA + (r * HSTRIDE + seg * 8) * 2, A + gm * K + kc + seg * 8);
        }
        #pragma unroll
        for (int p = 0; p < 2; p++) {       // B: 64 rows x 8 segs
            int i = tid + p * 256;
            int r = i >> 3, seg = i & 7;
            cp16s(offB + (r * HSTRIDE + seg * 8) * 2, Wt + (n0 + r) * K + kc + seg * 8);
        }
    };

    // ldmatrix per-lane address components (constant across chunks)
    const int l7  = lane & 7;
    const int l8  = (lane >> 3) & 1;
    const int l16 = lane >> 4;
    // A x4: matrices [rows lo/k lo, rows hi/k lo, rows lo/k hi, rows hi/k hi]
    const uint32_t aRowOff = (uint32_t)((wm * 32 + l7 + l8 * 8) * HSTRIDE + l16 * 8) * 2;
    // B x4 (tn pair): [tn rows/k lo, tn rows/k hi, tn+1 rows/k lo, tn+1 rows/k hi]
    const uint32_t bRowOff = (uint32_t)((wn * 32 + l7 + l16 * 8) * HSTRIDE + l8 * 8) * 2;

    auto computeStage = [&](int stage) {
        uint32_t As = sb + stage * (STAGE_H * 2);
        uint32_t Bsa = As + A_STAGE_H * 2;
        uint32_t aBase = As + aRowOff;
        uint32_t bBase = Bsa + bRowOff;
        #pragma unroll
        for (int kk = 0; kk < BKh; kk += 16) {
            uint32_t af[2][4], bf[4][2];
            ldsm4(af[0][0], af[0][1], af[0][2], af[0][3], aBase + kk * 2);
            ldsm4(af[1][0], af[1][1], af[1][2], af[1][3],
                  aBase + (16 * HSTRIDE + kk) * 2);
            ldsm4(bf[0][0], bf[0][1], bf[1][0], bf[1][1], bBase + kk * 2);
            ldsm4(bf[2][0], bf[2][1], bf[3][0], bf[3][1],
                  bBase + (16 * HSTRIDE + kk) * 2);
            #pragma unroll
            for (int tm = 0; tm < 2; tm++)
                #pragma unroll
                for (int tn = 0; tn < 4; tn++) {
                    asm volatile(
                        "mma.sync.aligned.m16n8k16.row.col.f32.f16.f16.f32 "
                        "{%0,%1,%2,%3}, {%4,%5,%6,%7}, {%8,%9}, {%0,%1,%2,%3};\n"
                        : "+f"(c[tm][tn][0]), "+f"(c[tm][tn][1]),
                          "+f"(c[tm][tn][2]), "+f"(c[tm][tn][3])
                        : "r"(af[tm][0]), "r"(af[tm][1]), "r"(af[tm][2]), "r"(af[tm][3]),
                          "r"(bf[tn][0]), "r"(bf[tn][1]));
                }
        }
    };

    const int KT = K / BKh;
    loadStage(0, 0);
    CP_COMMIT();
    int buf = 0;
    for (int ct = 0; ct < KT; ct++) {
        if (ct + 1 < KT) {
            loadStage(buf ^ 1, ct + 1);
            CP_COMMIT();
            CP_WAIT(1);
        } else {
            CP_WAIT(0);
        }
        __syncthreads();
        computeStage(buf);
        __syncthreads();
        buf ^= 1;
    }

    // epilogue
    #pragma unroll
    for (int tm = 0; tm < 2; tm++) {
        #pragma unroll
        for (int tn = 0; tn < 4; tn++) {
            int row0 = m0 + wm * 32 + tm * 16 + lq;
            int col = n0 + wn * 32 + tn * 8 + 2 * lr;
            #pragma unroll
            for (int half_i = 0; half_i < 2; half_i++) {
                int r = row0 + half_i * 8;
                if (r < M) {
                    float v0 = c[tm][tn][half_i * 2 + 0] + bias[col];
                    float v1 = c[tm][tn][half_i * 2 + 1] + bias[col + 1];
                    if (res) { v0 += res[r * N + col]; v1 += res[r * N + col + 1]; }
                    if (act) {
                        __half2 hv = __floats2half2_rn(gelu_f(v0), gelu_f(v1));
                        *(__half2*)((__half*)Cv + r * N + col) = hv;
                    } else {
                        float* C = (float*)Cv;
                        C[r * N + col] = v0;
                        C[r * N + col + 1] = v1;
                    }
                }
            }
        }
    }
}

// ---------------- sparse attention: warp per (b, query), fp16 output ----------------
__global__ void attn_kernel() {
    int gw = blockIdx.x * 8 + (threadIdx.x >> 5);
    if (gw >= BATCH * SEQL) return;
    int b = gw / SEQL;
    int l = gw - b * SEQL;
    int lane = threadIdx.x & 31;
    int row = b * SEQL + l;

    if (l == 0 || l == SEQL - 1) {
        #pragma unroll
        for (int t = 0; t < 8; t++)
            g_o[row * DMODEL + lane + 32 * t] = __float2half(g_v[row * DMODEL + lane + 32 * t]);
        return;
    }

    int r = g_rel[row];
    int cnt = g_cnt[b * NUM_PM + r];
    if (cnt > CAP) cnt = CAP;
    const int* lst = g_list + (b * NUM_PM + r) * CAP;

    const float scale = 0.17677669529663687f;
    float q8[8], o8[8], mx[8], sum[8];
    #pragma unroll
    for (int h = 0; h < 8; h++) {
        q8[h] = g_q[row * DMODEL + lane + 32 * h] * scale;
        o8[h] = 0.f; mx[h] = -1e30f; sum[h] = 0.f;
    }

    for (int i = 0; i < cnt; i++) {
        int krow = b * SEQL + lst[i];
        float k8[8], v8[8];
        #pragma unroll
        for (int t = 0; t < 8; t++) {
            k8[t] = g_k[krow * DMODEL + lane + 32 * t];
            v8[t] = g_v[krow * DMODEL + lane + 32 * t];
        }
        #pragma unroll
        for (int h = 0; h < 8; h++) {
            float d = q8[h] * k8[h];
            #pragma unroll
            for (int o = 16; o > 0; o >>= 1) d += __shfl_xor_sync(0xffffffffu, d, o);
            float nm = fmaxf(mx[h], d);
            float corr = __expf(mx[h] - nm);
            float p = __expf(d - nm);
            sum[h] = sum[h] * corr + p;
            o8[h] = o8[h] * corr + p * v8[h];
            mx[h] = nm;
        }
    }
    #pragma unroll
    for (int h = 0; h < 8; h++)
        g_o[row * DMODEL + lane + 32 * h] = __float2half(o8[h] / sum[h]);
}

// ---------------- output head ----------------
__global__ void out_kernel(const float* __restrict__ W_out, const float* __restrict__ b_out,
                           float* __restrict__ out) {
    int b = blockIdx.y;
    int warp = threadIdx.x >> 5;
    int lane = threadIdx.x & 31;
    int j = blockIdx.x * 8 + warp;
    if (j >= NUM_VM) return;
    int row = b * SEQL + NUM_PM + 1 + j;
    float acc = 0.f;
    #pragma unroll
    for (int d = lane; d < DMODEL; d += 32)
        acc += g_x[row * DMODEL + d] * W_out[d];
    #pragma unroll
    for (int o = 16; o > 0; o >>= 1) acc += __shfl_xor_sync(0xffffffffu, acc, o);
    if (lane == 0) out[b * NUM_VM + j] = acc + b_out[0];
}

// ---------------- host launcher ----------------
extern "C" void kernel_launch(void* const* d_in, const int* in_sizes, int n_in,
                              void* d_out, int out_size) {
    const float* vm_states = (const float*)d_in[0];
    const float* num_step  = (const float*)d_in[1];
    const float* pm_states = (const float*)d_in[2];
    const float* W_pm = (const float*)d_in[3];
    const float* b_pm = (const float*)d_in[4];
    const float* W_vm = (const float*)d_in[5];
    const float* b_vm = (const float*)d_in[6];
    const float* critic = (const float*)d_in[7];
    const float* ln1_g = (const float*)d_in[8];
    const float* ln1_b = (const float*)d_in[9];
    const float* Wq = (const float*)d_in[10];
    const float* bq = (const float*)d_in[11];
    const float* Wk = (const float*)d_in[12];
    const float* bk = (const float*)d_in[13];
    const float* Wv = (const float*)d_in[14];
    const float* bv = (const float*)d_in[15];
    const float* Wo = (const float*)d_in[16];
    const float* bo = (const float*)d_in[17];
    const float* ln2_g = (const float*)d_in[18];
    const float* ln2_b = (const float*)d_in[19];
    const float* W1 = (const float*)d_in[20];
    const float* b1 = (const float*)d_in[21];
    const float* W2 = (const float*)d_in[22];
    const float* b2 = (const float*)d_in[23];
    const float* W_out = (const float*)d_in[24];
    const float* b_out = (const float*)d_in[25];
    float* out = (float*)d_out;

    void *ph, *pq, *pk, *pv, *po, *pf, *px;
    void *pWq, *pWk, *pWv, *pWo, *pW1, *pW2;
    cudaGetSymbolAddress(&px, g_x);
    cudaGetSymbolAddress(&ph, g_h);
    cudaGetSymbolAddress(&pq, g_q);
    cudaGetSymbolAddress(&pk, g_k);
    cudaGetSymbolAddress(&pv, g_v);
    cudaGetSymbolAddress(&po, g_o);
    cudaGetSymbolAddress(&pf, g_ffn);
    cudaGetSymbolAddress(&pWq, g_Wqt);
    cudaGetSymbolAddress(&pWk, g_Wkt);
    cudaGetSymbolAddress(&pWv, g_Wvt);
    cudaGetSymbolAddress(&pWo, g_Wot);
    cudaGetSymbolAddress(&pW1, g_W1t);
    cudaGetSymbolAddress(&pW2, g_W2t);
    float* x = (float*)px;
    __half* h = (__half*)ph;
    float* q = (float*)pq;
    float* k = (float*)pk;
    float* v = (float*)pv;
    __half* o = (__half*)po;
    __half* f = (__half*)pf;
    __half* rWq = (__half*)pWq;
    __half* rWk = (__half*)pWk;
    __half* rWv = (__half*)pWv;
    __half* rWo = (__half*)pWo;
    __half* rW1 = (__half*)pW1;
    __half* rW2 = (__half*)pW2;

    cudaFuncSetAttribute(gemm_h, cudaFuncAttributeMaxDynamicSharedMemorySize, GEMM_SMEM_H);

    // all 6 weight transposes in one launch
    transpose_all<<<2304, dim3(32, 8)>>>(Wq, Wk, Wv, Wo, W1, W2);

    embed_kernel<<<dim3(SEQL, BATCH), DMODEL>>>(vm_states, num_step, pm_states,
                                                W_pm, b_pm, W_vm, b_vm, critic);
    build_init<<<(BATCH * NUM_PM + 255) / 256, 256>>>();
    build_vm<<<(BATCH * NUM_VM + 255) / 256, 256>>>(vm_states);

    const int M = MROWS;
    const int gridM = (M + 127) / 128;              // 82
    dim3 gQKV(DMODEL / 64, gridM, 3);               // (4, 82, 3)
    dim3 g256(DMODEL / 64, gridM, 1);               // (4, 82)
    dim3 g1024(DFF / 64, gridM, 1);                 // (16, 82)
    dim3 gln((MROWS + 7) / 8);
    dim3 gattn((BATCH * SEQL + 7) / 8);

    for (int l = 0; l < NLAYER; l++) {
        ln_kernel<<<gln, 256>>>(ln1_g + l * DMODEL, ln1_b + l * DMODEL);
        gemm_h<<<gQKV, 256, GEMM_SMEM_H>>>(h,
            rWq + l * DMODEL * DMODEL, rWk + l * DMODEL * DMODEL, rWv + l * DMODEL * DMODEL,
            bq + l * DMODEL, bk + l * DMODEL, bv + l * DMODEL,
            q, k, v, nullptr, M, DMODEL, DMODEL, 0);
        attn_kernel<<<gattn, 256>>>();
        gemm_h<<<g256, 256, GEMM_SMEM_H>>>(o,
            rWo + l * DMODEL * DMODEL, rWo + l * DMODEL * DMODEL, rWo + l * DMODEL * DMODEL,
            bo + l * DMODEL, bo + l * DMODEL, bo + l * DMODEL,
            x, x, x, x, M, DMODEL, DMODEL, 0);
        ln_kernel<<<gln, 256>>>(ln2_g + l * DMODEL, ln2_b + l * DMODEL);
        gemm_h<<<g1024, 256, GEMM_SMEM_H>>>(h,
            rW1 + l * DMODEL * DFF, rW1 + l * DMODEL * DFF, rW1 + l * DMODEL * DFF,
            b1 + l * DFF, b1 + l * DFF, b1 + l * DFF,
            f, f, f, nullptr, M, DFF, DMODEL, 1);
        gemm_h<<<g256, 256, GEMM_SMEM_H>>>(f,
            rW2 + l * DFF * DMODEL, rW2 + l * DFF * DMODEL, rW2 + l * DFF * DMODEL,
            b2 + l * DMODEL, b2 + l * DMODEL, b2 + l * DMODEL,
            x, x, x, x, M, DMODEL, DFF, 0);
    }

    out_kernel<<<dim3((NUM_VM + 7) / 8, BATCH), 256>>>(W_out, b_out, out);
}

// round 15
// speedup vs baseline: 1.4956x; 1.0368x over previous
#include <cuda_runtime.h>
#include <cuda_fp16.h>
#include <cstdint>

#define BATCH 8
#define NUM_PM 300
#define NUM_VM 1000
#define PM_COV 8
#define DMODEL 256
#define NHEAD 8
#define DHEAD 32
#define DFF 1024
#define NLAYER 3
#define SEQL (NUM_PM + NUM_VM + 2)   // 1302
#define MROWS (BATCH * SEQL)          // 10416
#define CAP 64

// ---------------- static scratch ----------------
__device__ float  g_x[MROWS * DMODEL];
__device__ __half g_h[MROWS * DMODEL];
__device__ __half g_q[MROWS * DMODEL];
__device__ __half g_k[MROWS * DMODEL];
__device__ __half g_v[MROWS * DMODEL];
__device__ __half g_o[MROWS * DMODEL];
__device__ __half g_ffn[MROWS * DFF];
__device__ int    g_rel[MROWS];
__device__ int    g_cnt[BATCH * NUM_PM];
__device__ int    g_list[BATCH * NUM_PM * CAP];
// transposed + fp16 weights, [N][K] K-major
__device__ __half g_Wqt[NLAYER * DMODEL * DMODEL];
__device__ __half g_Wkt[NLAYER * DMODEL * DMODEL];
__device__ __half g_Wvt[NLAYER * DMODEL * DMODEL];
__device__ __half g_Wot[NLAYER * DMODEL * DMODEL];
__device__ __half g_W1t[NLAYER * DMODEL * DFF];
__device__ __half g_W2t[NLAYER * DFF * DMODEL];

__device__ __forceinline__ uint32_t h2_u32(__half2 h) {
    union { __half2 h2; uint32_t u; } cv;
    cv.h2 = h;
    return cv.u;
}

// ---------------- embed + rel ----------------
__global__ void embed_kernel(const float* __restrict__ vm_states,
                             const float* __restrict__ num_step,
                             const float* __restrict__ pm_states,
                             const float* __restrict__ W_pm, const float* __restrict__ b_pm,
                             const float* __restrict__ W_vm, const float* __restrict__ b_vm,
                             const float* __restrict__ critic) {
    int b = blockIdx.y;
    int l = blockIdx.x;
    int d = threadIdx.x;
    float val;
    if (l == 0) {
        val = num_step[b];
    } else if (l <= NUM_PM) {
        const float* pm = pm_states + (b * NUM_PM + (l - 1)) * PM_COV;
        float acc = b_pm[d];
        #pragma unroll
        for (int c = 0; c < PM_COV; c++) acc += pm[c] * W_pm[c * DMODEL + d];
        val = acc;
    } else if (l <= NUM_PM + NUM_VM) {
        const float* vm = vm_states + (b * NUM_VM + (l - 1 - NUM_PM)) * 7;
        float acc = b_vm[d];
        #pragma unroll
        for (int c = 0; c < 6; c++) acc += vm[c] * W_vm[c * DMODEL + d];
        val = acc;
    } else {
        val = critic[d];
    }
    g_x[(b * SEQL + l) * DMODEL + d] = val;
    if (d == 0) {
        int r = -100;
        if (l >= 1 && l <= NUM_PM) r = l - 1;
        else if (l > NUM_PM && l < SEQL - 1)
            r = (int)vm_states[(b * NUM_VM + (l - 1 - NUM_PM)) * 7 + 6];
        g_rel[b * SEQL + l] = r;
    }
}

// ---------------- group list build ----------------
__global__ void build_init() {
    int i = blockIdx.x * 256 + threadIdx.x;
    if (i >= BATCH * NUM_PM) return;
    int r = i % NUM_PM;
    g_cnt[i] = 1;
    g_list[i * CAP] = 1 + r;
}

__global__ void build_vm(const float* __restrict__ vm_states) {
    int i = blockIdx.x * 256 + threadIdx.x;
    if (i >= BATCH * NUM_VM) return;
    int b = i / NUM_VM, j = i % NUM_VM;
    int r = (int)vm_states[(b * NUM_VM + j) * 7 + 6];
    int p = atomicAdd(&g_cnt[b * NUM_PM + r], 1);
    if (p < CAP) g_list[(b * NUM_PM + r) * CAP + p] = NUM_PM + 1 + j;
}

// ---------------- fused weight transpose + fp16: all 6 weights, one launch ----------------
__global__ void transpose_all(const float* __restrict__ Wq, const float* __restrict__ Wk,
                              const float* __restrict__ Wv, const float* __restrict__ Wo,
                              const float* __restrict__ W1, const float* __restrict__ W2) {
    __shared__ float t[32][33];
    int bid = blockIdx.x;
    const float* src;
    __half* dst;
    int K, N, ti;
    if (bid < 768) {
        int w = bid / 192;
        ti = bid % 192;
        src = (w == 0) ? Wq : (w == 1) ? Wk : (w == 2) ? Wv : Wo;
        dst = (w == 0) ? g_Wqt : (w == 1) ? g_Wkt : (w == 2) ? g_Wvt : g_Wot;
        K = DMODEL; N = DMODEL;
    } else if (bid < 1536) {
        ti = bid - 768; src = W1; dst = g_W1t; K = DMODEL; N = DFF;
    } else {
        ti = bid - 1536; src = W2; dst = g_W2t; K = DFF; N = DMODEL;
    }
    int tilesN = N >> 5;
    int perLayer = (K >> 5) * tilesN;
    int layer = ti / perLayer;
    int tt = ti - layer * perLayer;
    int k0 = (tt / tilesN) << 5, n0 = (tt % tilesN) << 5;
    const float* s = src + layer * K * N;
    __half* d = dst + layer * K * N;
    int tx = threadIdx.x, ty = threadIdx.y;
    #pragma unroll
    for (int j = 0; j < 32; j += 8)
        t[ty + j][tx] = s[(k0 + ty + j) * N + n0 + tx];
    __syncthreads();
    #pragma unroll
    for (int j = 0; j < 32; j += 8)
        d[(n0 + ty + j) * K + k0 + tx] = __float2half(t[tx][ty + j]);
}

// ---------------- layernorm: warp per row, fp16 output ----------------
__global__ void ln_kernel(const float* __restrict__ gamma, const float* __restrict__ beta) {
    int row = blockIdx.x * 8 + (threadIdx.x >> 5);
    if (row >= MROWS) return;
    int lane = threadIdx.x & 31;
    const float4* xr = (const float4*)(g_x + row * DMODEL) + lane * 2;
    float4 a = xr[0], c4 = xr[1];
    float v8[8] = {a.x, a.y, a.z, a.w, c4.x, c4.y, c4.z, c4.w};
    float s = 0.f;
    #pragma unroll
    for (int t = 0; t < 8; t++) s += v8[t];
    #pragma unroll
    for (int o = 16; o > 0; o >>= 1) s += __shfl_xor_sync(0xffffffffu, s, o);
    float mean = s * (1.0f / DMODEL);
    float vs = 0.f;
    #pragma unroll
    for (int t = 0; t < 8; t++) { v8[t] -= mean; vs += v8[t] * v8[t]; }
    #pragma unroll
    for (int o = 16; o > 0; o >>= 1) vs += __shfl_xor_sync(0xffffffffu, vs, o);
    float r = rsqrtf(vs * (1.0f / DMODEL) + 1e-5f);
    const float4* gg = (const float4*)gamma + lane * 2;
    const float4* bb = (const float4*)beta + lane * 2;
    float4 g0 = gg[0], g1 = gg[1], b0 = bb[0], b1 = bb[1];
    float ge[8] = {g0.x, g0.y, g0.z, g0.w, g1.x, g1.y, g1.z, g1.w};
    float be[8] = {b0.x, b0.y, b0.z, b0.w, b1.x, b1.y, b1.z, b1.w};
    uint4 pack;
    pack.x = h2_u32(__floats2half2_rn(v8[0] * r * ge[0] + be[0], v8[1] * r * ge[1] + be[1]));
    pack.y = h2_u32(__floats2half2_rn(v8[2] * r * ge[2] + be[2], v8[3] * r * ge[3] + be[3]));
    pack.z = h2_u32(__floats2half2_rn(v8[4] * r * ge[4] + be[4], v8[5] * r * ge[5] + be[5]));
    pack.w = h2_u32(__floats2half2_rn(v8[6] * r * ge[6] + be[6], v8[7] * r * ge[7] + be[7]));
    *((uint4*)(g_h + row * DMODEL) + lane) = pack;
}

// ---------------- GELU (tanh approx) ----------------
__device__ __forceinline__ float gelu_f(float x) {
    float x3 = x * x * x;
    float t = tanhf(0.7978845608028654f * (x + 0.044715f * x3));
    return 0.5f * x * (1.0f + t);
}

// ================= fp16 mma.sync GEMM =================
// CTA tile 128x64, 8 warps (4x2), warp tile 32x32, BK=64 halfs,
// 2-stage double buffer, 4 CTAs/SM, ldmatrix fragment loads.
#define BKh 64
#define HSTRIDE 72
#define A_STAGE_H (128 * HSTRIDE)              // 9216 halfs (A: 128 rows)
#define B_STAGE_H (64 * HSTRIDE)               // 4608 halfs (B: 64 rows)
#define STAGE_H   (A_STAGE_H + B_STAGE_H)      // 13824 halfs = 27648 B
#define NSTAGE 2
#define GEMM_SMEM_H (NSTAGE * STAGE_H * 2)     // 55296 bytes -> 4 CTAs/SM

__device__ __forceinline__ void cp16s(uint32_t saddr, const void* g) {
    asm volatile("cp.async.cg.shared.global [%0], [%1], 16;\n" :: "r"(saddr), "l"(g));
}
#define CP_COMMIT() asm volatile("cp.async.commit_group;\n" ::: "memory")
#define CP_WAIT(n)  asm volatile("cp.async.wait_group %0;\n" :: "n"(n) : "memory")
__device__ __forceinline__ uint32_t smem_u32(const void* p) {
    uint32_t a;
    asm("{ .reg .u64 t; cvta.to.shared.u64 t, %1; cvt.u32.u64 %0, t; }" : "=r"(a) : "l"(p));
    return a;
}
__device__ __forceinline__ void ldsm4(uint32_t& r0, uint32_t& r1, uint32_t& r2, uint32_t& r3,
                                      uint32_t addr) {
    asm volatile("ldmatrix.sync.aligned.m8n8.x4.shared.b16 {%0,%1,%2,%3}, [%4];"
                 : "=r"(r0), "=r"(r1), "=r"(r2), "=r"(r3) : "r"(addr));
}

// z-dim selects among up to 3 weight/bias/output sets (QKV fusion).
// outHalf: store C as __half (act path always stores half).
__global__ void __launch_bounds__(256, 4)
gemm_h(const __half* __restrict__ A,
       const __half* __restrict__ Wt0, const __half* __restrict__ Wt1,
       const __half* __restrict__ Wt2,
       const float* __restrict__ bias0, const float* __restrict__ bias1,
       const float* __restrict__ bias2,
       void* __restrict__ C0, void* __restrict__ C1, void* __restrict__ C2,
       const float* __restrict__ res,
       int M, int N, int K, int act, int outHalf) {
    const __half* Wt  = (blockIdx.z == 0) ? Wt0   : (blockIdx.z == 1) ? Wt1   : Wt2;
    const float* bias = (blockIdx.z == 0) ? bias0 : (blockIdx.z == 1) ? bias1 : bias2;
    void* Cv          = (blockIdx.z == 0) ? C0    : (blockIdx.z == 1) ? C1    : C2;

    extern __shared__ __half smh[];
    const int tid = threadIdx.x;
    const int m0 = blockIdx.y * 128;
    const int n0 = blockIdx.x * 64;
    const int lane = tid & 31;
    const int warp = tid >> 5;
    const int wm = warp >> 1;          // 0..3
    const int wn = warp & 1;           // 0..1
    const int lq = lane >> 2;          // 0..7
    const int lr = lane & 3;           // 0..3

    float c[2][4][4];
    #pragma unroll
    for (int i = 0; i < 2; i++)
        #pragma unroll
        for (int j = 0; j < 4; j++)
            #pragma unroll
            for (int p = 0; p < 4; p++) c[i][j][p] = 0.f;

    uint32_t sb = smem_u32(smh);

    auto loadStage = [&](int stage, int ct) {
        int kc = ct * BKh;
        uint32_t offA = sb + stage * (STAGE_H * 2);
        uint32_t offB = offA + A_STAGE_H * 2;
        #pragma unroll
        for (int p = 0; p < 4; p++) {       // A: 128 rows x 8 segs
            int i = tid + p * 256;
            int r = i >> 3, seg = i & 7;
            int gm = m0 + r;
            if (gm >= M) gm = M - 1;
            cp16s(offA + (r * HSTRIDE + seg * 8) * 2, A + gm * K + kc + seg * 8);
        }
        #pragma unroll
        for (int p = 0; p < 2; p++) {       // B: 64 rows x 8 segs
            int i = tid + p * 256;
            int r = i >> 3, seg = i & 7;
            cp16s(offB + (r * HSTRIDE + seg * 8) * 2, Wt + (n0 + r) * K + kc + seg * 8);
        }
    };

    // ldmatrix per-lane address components (constant across chunks)
    const int l7  = lane & 7;
    const int l8  = (lane >> 3) & 1;
    const int l16 = lane >> 4;
    const uint32_t aRowOff = (uint32_t)((wm * 32 + l7 + l8 * 8) * HSTRIDE + l16 * 8) * 2;
    const uint32_t bRowOff = (uint32_t)((wn * 32 + l7 + l16 * 8) * HSTRIDE + l8 * 8) * 2;

    auto computeStage = [&](int stage) {
        uint32_t As = sb + stage * (STAGE_H * 2);
        uint32_t Bsa = As + A_STAGE_H * 2;
        uint32_t aBase = As + aRowOff;
        uint32_t bBase = Bsa + bRowOff;
        #pragma unroll
        for (int kk = 0; kk < BKh; kk += 16) {
            uint32_t af[2][4], bf[4][2];
            ldsm4(af[0][0], af[0][1], af[0][2], af[0][3], aBase + kk * 2);
            ldsm4(af[1][0], af[1][1], af[1][2], af[1][3],
                  aBase + (16 * HSTRIDE + kk) * 2);
            ldsm4(bf[0][0], bf[0][1], bf[1][0], bf[1][1], bBase + kk * 2);
            ldsm4(bf[2][0], bf[2][1], bf[3][0], bf[3][1],
                  bBase + (16 * HSTRIDE + kk) * 2);
            #pragma unroll
            for (int tm = 0; tm < 2; tm++)
                #pragma unroll
                for (int tn = 0; tn < 4; tn++) {
                    asm volatile(
                        "mma.sync.aligned.m16n8k16.row.col.f32.f16.f16.f32 "
                        "{%0,%1,%2,%3}, {%4,%5,%6,%7}, {%8,%9}, {%0,%1,%2,%3};\n"
                        : "+f"(c[tm][tn][0]), "+f"(c[tm][tn][1]),
                          "+f"(c[tm][tn][2]), "+f"(c[tm][tn][3])
                        : "r"(af[tm][0]), "r"(af[tm][1]), "r"(af[tm][2]), "r"(af[tm][3]),
                          "r"(bf[tn][0]), "r"(bf[tn][1]));
                }
        }
    };

    const int KT = K / BKh;
    loadStage(0, 0);
    CP_COMMIT();
    int buf = 0;
    for (int ct = 0; ct < KT; ct++) {
        if (ct + 1 < KT) {
            loadStage(buf ^ 1, ct + 1);
            CP_COMMIT();
            CP_WAIT(1);
        } else {
            CP_WAIT(0);
        }
        __syncthreads();
        computeStage(buf);
        __syncthreads();
        buf ^= 1;
    }

    // epilogue
    #pragma unroll
    for (int tm = 0; tm < 2; tm++) {
        #pragma unroll
        for (int tn = 0; tn < 4; tn++) {
            int row0 = m0 + wm * 32 + tm * 16 + lq;
            int col = n0 + wn * 32 + tn * 8 + 2 * lr;
            #pragma unroll
            for (int half_i = 0; half_i < 2; half_i++) {
                int r = row0 + half_i * 8;
                if (r < M) {
                    float v0 = c[tm][tn][half_i * 2 + 0] + bias[col];
                    float v1 = c[tm][tn][half_i * 2 + 1] + bias[col + 1];
                    if (res) { v0 += res[r * N + col]; v1 += res[r * N + col + 1]; }
                    if (act) { v0 = gelu_f(v0); v1 = gelu_f(v1); }
                    if (act || outHalf) {
                        __half2 hv = __floats2half2_rn(v0, v1);
                        *(__half2*)((__half*)Cv + r * N + col) = hv;
                    } else {
                        float* C = (float*)Cv;
                        C[r * N + col] = v0;
                        C[r * N + col + 1] = v1;
                    }
                }
            }
        }
    }
}

// ---------------- sparse attention: warp per (b, query), fp16 q/k/v ----------------
__global__ void attn_kernel() {
    int gw = blockIdx.x * 8 + (threadIdx.x >> 5);
    if (gw >= BATCH * SEQL) return;
    int b = gw / SEQL;
    int l = gw - b * SEQL;
    int lane = threadIdx.x & 31;
    int row = b * SEQL + l;

    if (l == 0 || l == SEQL - 1) {
        #pragma unroll
        for (int t = 0; t < 8; t++)
            g_o[row * DMODEL + lane + 32 * t] = g_v[row * DMODEL + lane + 32 * t];
        return;
    }

    int r = g_rel[row];
    int cnt = g_cnt[b * NUM_PM + r];
    if (cnt > CAP) cnt = CAP;
    const int* lst = g_list + (b * NUM_PM + r) * CAP;

    const float scale = 0.17677669529663687f;
    float q8[8], o8[8], mx[8], sum[8];
    #pragma unroll
    for (int h = 0; h < 8; h++) {
        q8[h] = __half2float(g_q[row * DMODEL + lane + 32 * h]) * scale;
        o8[h] = 0.f; mx[h] = -1e30f; sum[h] = 0.f;
    }

    for (int i = 0; i < cnt; i++) {
        int krow = b * SEQL + lst[i];
        float k8[8], v8[8];
        #pragma unroll
        for (int t = 0; t < 8; t++) {
            k8[t] = __half2float(g_k[krow * DMODEL + lane + 32 * t]);
            v8[t] = __half2float(g_v[krow * DMODEL + lane + 32 * t]);
        }
        #pragma unroll
        for (int h = 0; h < 8; h++) {
            float d = q8[h] * k8[h];
            #pragma unroll
            for (int o = 16; o > 0; o >>= 1) d += __shfl_xor_sync(0xffffffffu, d, o);
            float nm = fmaxf(mx[h], d);
            float corr = __expf(mx[h] - nm);
            float p = __expf(d - nm);
            sum[h] = sum[h] * corr + p;
            o8[h] = o8[h] * corr + p * v8[h];
            mx[h] = nm;
        }
    }
    #pragma unroll
    for (int h = 0; h < 8; h++)
        g_o[row * DMODEL + lane + 32 * h] = __float2half(o8[h] / sum[h]);
}

// ---------------- output head ----------------
__global__ void out_kernel(const float* __restrict__ W_out, const float* __restrict__ b_out,
                           float* __restrict__ out) {
    int b = blockIdx.y;
    int warp = threadIdx.x >> 5;
    int lane = threadIdx.x & 31;
    int j = blockIdx.x * 8 + warp;
    if (j >= NUM_VM) return;
    int row = b * SEQL + NUM_PM + 1 + j;
    float acc = 0.f;
    #pragma unroll
    for (int d = lane; d < DMODEL; d += 32)
        acc += g_x[row * DMODEL + d] * W_out[d];
    #pragma unroll
    for (int o = 16; o > 0; o >>= 1) acc += __shfl_xor_sync(0xffffffffu, acc, o);
    if (lane == 0) out[b * NUM_VM + j] = acc + b_out[0];
}

// ---------------- host launcher ----------------
extern "C" void kernel_launch(void* const* d_in, const int* in_sizes, int n_in,
                              void* d_out, int out_size) {
    const float* vm_states = (const float*)d_in[0];
    const float* num_step  = (const float*)d_in[1];
    const float* pm_states = (const float*)d_in[2];
    const float* W_pm = (const float*)d_in[3];
    const float* b_pm = (const float*)d_in[4];
    const float* W_vm = (const float*)d_in[5];
    const float* b_vm = (const float*)d_in[6];
    const float* critic = (const float*)d_in[7];
    const float* ln1_g = (const float*)d_in[8];
    const float* ln1_b = (const float*)d_in[9];
    const float* Wq = (const float*)d_in[10];
    const float* bq = (const float*)d_in[11];
    const float* Wk = (const float*)d_in[12];
    const float* bk = (const float*)d_in[13];
    const float* Wv = (const float*)d_in[14];
    const float* bv = (const float*)d_in[15];
    const float* Wo = (const float*)d_in[16];
    const float* bo = (const float*)d_in[17];
    const float* ln2_g = (const float*)d_in[18];
    const float* ln2_b = (const float*)d_in[19];
    const float* W1 = (const float*)d_in[20];
    const float* b1 = (const float*)d_in[21];
    const float* W2 = (const float*)d_in[22];
    const float* b2 = (const float*)d_in[23];
    const float* W_out = (const float*)d_in[24];
    const float* b_out = (const float*)d_in[25];
    float* out = (float*)d_out;

    void *ph, *pq, *pk, *pv, *po, *pf, *px;
    void *pWq, *pWk, *pWv, *pWo, *pW1, *pW2;
    cudaGetSymbolAddress(&px, g_x);
    cudaGetSymbolAddress(&ph, g_h);
    cudaGetSymbolAddress(&pq, g_q);
    cudaGetSymbolAddress(&pk, g_k);
    cudaGetSymbolAddress(&pv, g_v);
    cudaGetSymbolAddress(&po, g_o);
    cudaGetSymbolAddress(&pf, g_ffn);
    cudaGetSymbolAddress(&pWq, g_Wqt);
    cudaGetSymbolAddress(&pWk, g_Wkt);
    cudaGetSymbolAddress(&pWv, g_Wvt);
    cudaGetSymbolAddress(&pWo, g_Wot);
    cudaGetSymbolAddress(&pW1, g_W1t);
    cudaGetSymbolAddress(&pW2, g_W2t);
    float* x = (float*)px;
    __half* h = (__half*)ph;
    __half* q = (__half*)pq;
    __half* k = (__half*)pk;
    __half* v = (__half*)pv;
    __half* o = (__half*)po;
    __half* f = (__half*)pf;
    __half* rWq = (__half*)pWq;
    __half* rWk = (__half*)pWk;
    __half* rWv = (__half*)pWv;
    __half* rWo = (__half*)pWo;
    __half* rW1 = (__half*)pW1;
    __half* rW2 = (__half*)pW2;

    cudaFuncSetAttribute(gemm_h, cudaFuncAttributeMaxDynamicSharedMemorySize, GEMM_SMEM_H);

    // all 6 weight transposes in one launch
    transpose_all<<<2304, dim3(32, 8)>>>(Wq, Wk, Wv, Wo, W1, W2);

    embed_kernel<<<dim3(SEQL, BATCH), DMODEL>>>(vm_states, num_step, pm_states,
                                                W_pm, b_pm, W_vm, b_vm, critic);
    build_init<<<(BATCH * NUM_PM + 255) / 256, 256>>>();
    build_vm<<<(BATCH * NUM_VM + 255) / 256, 256>>>(vm_states);

    const int M = MROWS;
    const int gridM = (M + 127) / 128;              // 82
    dim3 gQKV(DMODEL / 64, gridM, 3);               // (4, 82, 3)
    dim3 g256(DMODEL / 64, gridM, 1);               // (4, 82)
    dim3 g1024(DFF / 64, gridM, 1);                 // (16, 82)
    dim3 gln((MROWS + 7) / 8);
    dim3 gattn((BATCH * SEQL + 7) / 8);

    for (int l = 0; l < NLAYER; l++) {
        ln_kernel<<<gln, 256>>>(ln1_g + l * DMODEL, ln1_b + l * DMODEL);
        gemm_h<<<gQKV, 256, GEMM_SMEM_H>>>(h,
            rWq + l * DMODEL * DMODEL, rWk + l * DMODEL * DMODEL, rWv + l * DMODEL * DMODEL,
            bq + l * DMODEL, bk + l * DMODEL, bv + l * DMODEL,
            q, k, v, nullptr, M, DMODEL, DMODEL, 0, 1);
        attn_kernel<<<gattn, 256>>>();
        gemm_h<<<g256, 256, GEMM_SMEM_H>>>(o,
            rWo + l * DMODEL * DMODEL, rWo + l * DMODEL * DMODEL, rWo + l * DMODEL * DMODEL,
            bo + l * DMODEL, bo + l * DMODEL, bo + l * DMODEL,
            x, x, x, x, M, DMODEL, DMODEL, 0, 0);
        ln_kernel<<<gln, 256>>>(ln2_g + l * DMODEL, ln2_b + l * DMODEL);
        gemm_h<<<g1024, 256, GEMM_SMEM_H>>>(h,
            rW1 + l * DMODEL * DFF, rW1 + l * DMODEL * DFF, rW1 + l * DMODEL * DFF,
            b1 + l * DFF, b1 + l * DFF, b1 + l * DFF,
            f, f, f, nullptr, M, DFF, DMODEL, 1, 1);
        gemm_h<<<g256, 256, GEMM_SMEM_H>>>(f,
            rW2 + l * DFF * DMODEL, rW2 + l * DFF * DMODEL, rW2 + l * DFF * DMODEL,
            b2 + l * DMODEL, b2 + l * DMODEL, b2 + l * DMODEL,
            x, x, x, x, M, DMODEL, DFF, 0, 0);
    }

    out_kernel<<<dim3((NUM_VM + 7) / 8, BATCH), 256>>>(W_out, b_out, out);
}

// round 16
// speedup vs baseline: 1.5896x; 1.0629x over previous
#include <cuda_runtime.h>
#include <cuda_fp16.h>
#include <cstdint>

#define BATCH 8
#define NUM_PM 300
#define NUM_VM 1000
#define PM_COV 8
#define DMODEL 256
#define NHEAD 8
#define DHEAD 32
#define DFF 1024
#define NLAYER 3
#define SEQL (NUM_PM + NUM_VM + 2)   // 1302
#define MROWS (BATCH * SEQL)          // 10416
#define CAP 64

// ---------------- static scratch ----------------
__device__ float  g_x[MROWS * DMODEL];
__device__ __half g_h[MROWS * DMODEL];
__device__ __half g_q[MROWS * DMODEL];
__device__ __half g_k[MROWS * DMODEL];
__device__ __half g_v[MROWS * DMODEL];
__device__ __half g_o[MROWS * DMODEL];
__device__ __half g_ffn[MROWS * DFF];
__device__ int    g_rel[MROWS];
__device__ int    g_cnt[BATCH * NUM_PM];
__device__ int    g_list[BATCH * NUM_PM * CAP];
// transposed + fp16 weights, [N][K] K-major
__device__ __half g_Wqt[NLAYER * DMODEL * DMODEL];
__device__ __half g_Wkt[NLAYER * DMODEL * DMODEL];
__device__ __half g_Wvt[NLAYER * DMODEL * DMODEL];
__device__ __half g_Wot[NLAYER * DMODEL * DMODEL];
__device__ __half g_W1t[NLAYER * DMODEL * DFF];
__device__ __half g_W2t[NLAYER * DFF * DMODEL];

__device__ __forceinline__ uint32_t h2_u32(__half2 h) {
    union { __half2 h2; uint32_t u; } cv;
    cv.h2 = h;
    return cv.u;
}

// ---------------- embed + rel + group-list init ----------------
__global__ void embed_kernel(const float* __restrict__ vm_states,
                             const float* __restrict__ num_step,
                             const float* __restrict__ pm_states,
                             const float* __restrict__ W_pm, const float* __restrict__ b_pm,
                             const float* __restrict__ W_vm, const float* __restrict__ b_vm,
                             const float* __restrict__ critic) {
    int b = blockIdx.y;
    int l = blockIdx.x;
    int d = threadIdx.x;
    float val;
    if (l == 0) {
        val = num_step[b];
    } else if (l <= NUM_PM) {
        const float* pm = pm_states + (b * NUM_PM + (l - 1)) * PM_COV;
        float acc = b_pm[d];
        #pragma unroll
        for (int c = 0; c < PM_COV; c++) acc += pm[c] * W_pm[c * DMODEL + d];
        val = acc;
    } else if (l <= NUM_PM + NUM_VM) {
        const float* vm = vm_states + (b * NUM_VM + (l - 1 - NUM_PM)) * 7;
        float acc = b_vm[d];
        #pragma unroll
        for (int c = 0; c < 6; c++) acc += vm[c] * W_vm[c * DMODEL + d];
        val = acc;
    } else {
        val = critic[d];
    }
    g_x[(b * SEQL + l) * DMODEL + d] = val;
    if (d == 0) {
        int r = -100;
        if (l >= 1 && l <= NUM_PM) {
            r = l - 1;
            // group-list init (was build_init kernel)
            g_cnt[b * NUM_PM + r] = 1;
            g_list[(b * NUM_PM + r) * CAP] = l;
        } else if (l > NUM_PM && l < SEQL - 1) {
            r = (int)vm_states[(b * NUM_VM + (l - 1 - NUM_PM)) * 7 + 6];
        }
        g_rel[b * SEQL + l] = r;
    }
}

__global__ void build_vm(const float* __restrict__ vm_states) {
    int i = blockIdx.x * 256 + threadIdx.x;
    if (i >= BATCH * NUM_VM) return;
    int b = i / NUM_VM, j = i % NUM_VM;
    int r = (int)vm_states[(b * NUM_VM + j) * 7 + 6];
    int p = atomicAdd(&g_cnt[b * NUM_PM + r], 1);
    if (p < CAP) g_list[(b * NUM_PM + r) * CAP + p] = NUM_PM + 1 + j;
}

// ---------------- fused weight transpose + fp16: all 6 weights, one launch ----------------
__global__ void transpose_all(const float* __restrict__ Wq, const float* __restrict__ Wk,
                              const float* __restrict__ Wv, const float* __restrict__ Wo,
                              const float* __restrict__ W1, const float* __restrict__ W2) {
    __shared__ float t[32][33];
    int bid = blockIdx.x;
    const float* src;
    __half* dst;
    int K, N, ti;
    if (bid < 768) {
        int w = bid / 192;
        ti = bid % 192;
        src = (w == 0) ? Wq : (w == 1) ? Wk : (w == 2) ? Wv : Wo;
        dst = (w == 0) ? g_Wqt : (w == 1) ? g_Wkt : (w == 2) ? g_Wvt : g_Wot;
        K = DMODEL; N = DMODEL;
    } else if (bid < 1536) {
        ti = bid - 768; src = W1; dst = g_W1t; K = DMODEL; N = DFF;
    } else {
        ti = bid - 1536; src = W2; dst = g_W2t; K = DFF; N = DMODEL;
    }
    int tilesN = N >> 5;
    int perLayer = (K >> 5) * tilesN;
    int layer = ti / perLayer;
    int tt = ti - layer * perLayer;
    int k0 = (tt / tilesN) << 5, n0 = (tt % tilesN) << 5;
    const float* s = src + layer * K * N;
    __half* d = dst + layer * K * N;
    int tx = threadIdx.x, ty = threadIdx.y;
    #pragma unroll
    for (int j = 0; j < 32; j += 8)
        t[ty + j][tx] = s[(k0 + ty + j) * N + n0 + tx];
    __syncthreads();
    #pragma unroll
    for (int j = 0; j < 32; j += 8)
        d[(n0 + ty + j) * K + k0 + tx] = __float2half(t[tx][ty + j]);
}

// ---------------- layernorm: warp per row, fp16 output ----------------
__global__ void ln_kernel(const float* __restrict__ gamma, const float* __restrict__ beta) {
    int row = blockIdx.x * 8 + (threadIdx.x >> 5);
    if (row >= MROWS) return;
    int lane = threadIdx.x & 31;
    const float4* xr = (const float4*)(g_x + row * DMODEL) + lane * 2;
    float4 a = xr[0], c4 = xr[1];
    float v8[8] = {a.x, a.y, a.z, a.w, c4.x, c4.y, c4.z, c4.w};
    float s = 0.f;
    #pragma unroll
    for (int t = 0; t < 8; t++) s += v8[t];
    #pragma unroll
    for (int o = 16; o > 0; o >>= 1) s += __shfl_xor_sync(0xffffffffu, s, o);
    float mean = s * (1.0f / DMODEL);
    float vs = 0.f;
    #pragma unroll
    for (int t = 0; t < 8; t++) { v8[t] -= mean; vs += v8[t] * v8[t]; }
    #pragma unroll
    for (int o = 16; o > 0; o >>= 1) vs += __shfl_xor_sync(0xffffffffu, vs, o);
    float r = rsqrtf(vs * (1.0f / DMODEL) + 1e-5f);
    const float4* gg = (const float4*)gamma + lane * 2;
    const float4* bb = (const float4*)beta + lane * 2;
    float4 g0 = gg[0], g1 = gg[1], b0 = bb[0], b1 = bb[1];
    float ge[8] = {g0.x, g0.y, g0.z, g0.w, g1.x, g1.y, g1.z, g1.w};
    float be[8] = {b0.x, b0.y, b0.z, b0.w, b1.x, b1.y, b1.z, b1.w};
    uint4 pack;
    pack.x = h2_u32(__floats2half2_rn(v8[0] * r * ge[0] + be[0], v8[1] * r * ge[1] + be[1]));
    pack.y = h2_u32(__floats2half2_rn(v8[2] * r * ge[2] + be[2], v8[3] * r * ge[3] + be[3]));
    pack.z = h2_u32(__floats2half2_rn(v8[4] * r * ge[4] + be[4], v8[5] * r * ge[5] + be[5]));
    pack.w = h2_u32(__floats2half2_rn(v8[6] * r * ge[6] + be[6], v8[7] * r * ge[7] + be[7]));
    *((uint4*)(g_h + row * DMODEL) + lane) = pack;
}

// ---------------- GELU (tanh approx) ----------------
__device__ __forceinline__ float gelu_f(float x) {
    float x3 = x * x * x;
    float t = tanhf(0.7978845608028654f * (x + 0.044715f * x3));
    return 0.5f * x * (1.0f + t);
}

// ================= fp16 mma.sync GEMM =================
// CTA tile 128x64, 8 warps (4x2), warp tile 32x32, BK=64 halfs,
// 2-stage double buffer, 4 CTAs/SM, ldmatrix fragment loads.
#define BKh 64
#define HSTRIDE 72
#define A_STAGE_H (128 * HSTRIDE)
#define B_STAGE_H (64 * HSTRIDE)
#define STAGE_H   (A_STAGE_H + B_STAGE_H)
#define NSTAGE 2
#define GEMM_SMEM_H (NSTAGE * STAGE_H * 2)     // 55296 bytes -> 4 CTAs/SM

__device__ __forceinline__ void cp16s(uint32_t saddr, const void* g) {
    asm volatile("cp.async.cg.shared.global [%0], [%1], 16;\n" :: "r"(saddr), "l"(g));
}
#define CP_COMMIT() asm volatile("cp.async.commit_group;\n" ::: "memory")
#define CP_WAIT(n)  asm volatile("cp.async.wait_group %0;\n" :: "n"(n) : "memory")
__device__ __forceinline__ uint32_t smem_u32(const void* p) {
    uint32_t a;
    asm("{ .reg .u64 t; cvta.to.shared.u64 t, %1; cvt.u32.u64 %0, t; }" : "=r"(a) : "l"(p));
    return a;
}
__device__ __forceinline__ void ldsm4(uint32_t& r0, uint32_t& r1, uint32_t& r2, uint32_t& r3,
                                      uint32_t addr) {
    asm volatile("ldmatrix.sync.aligned.m8n8.x4.shared.b16 {%0,%1,%2,%3}, [%4];"
                 : "=r"(r0), "=r"(r1), "=r"(r2), "=r"(r3) : "r"(addr));
}

// z-dim selects among up to 3 weight/bias/output sets (QKV fusion).
__global__ void __launch_bounds__(256, 4)
gemm_h(const __half* __restrict__ A,
       const __half* __restrict__ Wt0, const __half* __restrict__ Wt1,
       const __half* __restrict__ Wt2,
       const float* __restrict__ bias0, const float* __restrict__ bias1,
       const float* __restrict__ bias2,
       void* __restrict__ C0, void* __restrict__ C1, void* __restrict__ C2,
       const float* __restrict__ res,
       int M, int N, int K, int act, int outHalf) {
    const __half* Wt  = (blockIdx.z == 0) ? Wt0   : (blockIdx.z == 1) ? Wt1   : Wt2;
    const float* bias = (blockIdx.z == 0) ? bias0 : (blockIdx.z == 1) ? bias1 : bias2;
    void* Cv          = (blockIdx.z == 0) ? C0    : (blockIdx.z == 1) ? C1    : C2;

    extern __shared__ __half smh[];
    const int tid = threadIdx.x;
    const int m0 = blockIdx.y * 128;
    const int n0 = blockIdx.x * 64;
    const int lane = tid & 31;
    const int warp = tid >> 5;
    const int wm = warp >> 1;
    const int wn = warp & 1;
    const int lq = lane >> 2;
    const int lr = lane & 3;

    float c[2][4][4];
    #pragma unroll
    for (int i = 0; i < 2; i++)
        #pragma unroll
        for (int j = 0; j < 4; j++)
            #pragma unroll
            for (int p = 0; p < 4; p++) c[i][j][p] = 0.f;

    uint32_t sb = smem_u32(smh);

    auto loadStage = [&](int stage, int ct) {
        int kc = ct * BKh;
        uint32_t offA = sb + stage * (STAGE_H * 2);
        uint32_t offB = offA + A_STAGE_H * 2;
        #pragma unroll
        for (int p = 0; p < 4; p++) {
            int i = tid + p * 256;
            int r = i >> 3, seg = i & 7;
            int gm = m0 + r;
            if (gm >= M) gm = M - 1;
            cp16s(offA + (r * HSTRIDE + seg * 8) * 2, A + gm * K + kc + seg * 8);
        }
        #pragma unroll
        for (int p = 0; p < 2; p++) {
            int i = tid + p * 256;
            int r = i >> 3, seg = i & 7;
            cp16s(offB + (r * HSTRIDE + seg * 8) * 2, Wt + (n0 + r) * K + kc + seg * 8);
        }
    };

    const int l7  = lane & 7;
    const int l8  = (lane >> 3) & 1;
    const int l16 = lane >> 4;
    const uint32_t aRowOff = (uint32_t)((wm * 32 + l7 + l8 * 8) * HSTRIDE + l16 * 8) * 2;
    const uint32_t bRowOff = (uint32_t)((wn * 32 + l7 + l16 * 8) * HSTRIDE + l8 * 8) * 2;

    auto computeStage = [&](int stage) {
        uint32_t As = sb + stage * (STAGE_H * 2);
        uint32_t Bsa = As + A_STAGE_H * 2;
        uint32_t aBase = As + aRowOff;
        uint32_t bBase = Bsa + bRowOff;
        #pragma unroll
        for (int kk = 0; kk < BKh; kk += 16) {
            uint32_t af[2][4], bf[4][2];
            ldsm4(af[0][0], af[0][1], af[0][2], af[0][3], aBase + kk * 2);
            ldsm4(af[1][0], af[1][1], af[1][2], af[1][3],
                  aBase + (16 * HSTRIDE + kk) * 2);
            ldsm4(bf[0][0], bf[0][1], bf[1][0], bf[1][1], bBase + kk * 2);
            ldsm4(bf[2][0], bf[2][1], bf[3][0], bf[3][1],
                  bBase + (16 * HSTRIDE + kk) * 2);
            #pragma unroll
            for (int tm = 0; tm < 2; tm++)
                #pragma unroll
                for (int tn = 0; tn < 4; tn++) {
                    asm volatile(
                        "mma.sync.aligned.m16n8k16.row.col.f32.f16.f16.f32 "
                        "{%0,%1,%2,%3}, {%4,%5,%6,%7}, {%8,%9}, {%0,%1,%2,%3};\n"
                        : "+f"(c[tm][tn][0]), "+f"(c[tm][tn][1]),
                          "+f"(c[tm][tn][2]), "+f"(c[tm][tn][3])
                        : "r"(af[tm][0]), "r"(af[tm][1]), "r"(af[tm][2]), "r"(af[tm][3]),
                          "r"(bf[tn][0]), "r"(bf[tn][1]));
                }
        }
    };

    const int KT = K / BKh;
    loadStage(0, 0);
    CP_COMMIT();
    int buf = 0;
    for (int ct = 0; ct < KT; ct++) {
        if (ct + 1 < KT) {
            loadStage(buf ^ 1, ct + 1);
            CP_COMMIT();
            CP_WAIT(1);
        } else {
            CP_WAIT(0);
        }
        __syncthreads();
        computeStage(buf);
        __syncthreads();
        buf ^= 1;
    }

    // epilogue
    #pragma unroll
    for (int tm = 0; tm < 2; tm++) {
        #pragma unroll
        for (int tn = 0; tn < 4; tn++) {
            int row0 = m0 + wm * 32 + tm * 16 + lq;
            int col = n0 + wn * 32 + tn * 8 + 2 * lr;
            #pragma unroll
            for (int half_i = 0; half_i < 2; half_i++) {
                int r = row0 + half_i * 8;
                if (r < M) {
                    float v0 = c[tm][tn][half_i * 2 + 0] + bias[col];
                    float v1 = c[tm][tn][half_i * 2 + 1] + bias[col + 1];
                    if (res) { v0 += res[r * N + col]; v1 += res[r * N + col + 1]; }
                    if (act) { v0 = gelu_f(v0); v1 = gelu_f(v1); }
                    if (act || outHalf) {
                        __half2 hv = __floats2half2_rn(v0, v1);
                        *(__half2*)((__half*)Cv + r * N + col) = hv;
                    } else {
                        float* C = (float*)Cv;
                        C[r * N + col] = v0;
                        C[r * N + col + 1] = v1;
                    }
                }
            }
        }
    }
}

// ---------------- sparse attention: warp per (b, query), half2-vectorized ----------------
// Lane owns dims (2*lane, 2*lane+1) of each 64-dim block t; 16-lane half-warp = one head.
__global__ void attn_kernel() {
    int gw = blockIdx.x * 8 + (threadIdx.x >> 5);
    if (gw >= BATCH * SEQL) return;
    int b = gw / SEQL;
    int l = gw - b * SEQL;
    int lane = threadIdx.x & 31;
    int row = b * SEQL + l;

    if (l == 0 || l == SEQL - 1) {
        ((uint4*)(g_o + row * DMODEL))[lane] = ((const uint4*)(g_v + row * DMODEL))[lane];
        return;
    }

    int r = g_rel[row];
    int cnt = g_cnt[b * NUM_PM + r];
    if (cnt > CAP) cnt = CAP;
    const int* lst = g_list + (b * NUM_PM + r) * CAP;

    const float scale = 0.17677669529663687f;
    float2 q2[4], o2[4];
    float mx[4], sum[4];
    const __half2* qrow = (const __half2*)(g_q + row * DMODEL);
    #pragma unroll
    for (int t = 0; t < 4; t++) {
        float2 qf = __half22float2(qrow[lane + 32 * t]);
        q2[t] = make_float2(qf.x * scale, qf.y * scale);
        o2[t] = make_float2(0.f, 0.f);
        mx[t] = -1e30f; sum[t] = 0.f;
    }

    for (int i = 0; i < cnt; i++) {
        int krow = b * SEQL + lst[i];
        const __half2* kr = (const __half2*)(g_k + krow * DMODEL);
        const __half2* vr = (const __half2*)(g_v + krow * DMODEL);
        #pragma unroll
        for (int t = 0; t < 4; t++) {
            float2 kf = __half22float2(kr[lane + 32 * t]);
            float2 vf = __half22float2(vr[lane + 32 * t]);
            float d = q2[t].x * kf.x + q2[t].y * kf.y;
            // reduce within 16-lane group (one head per half-warp)
            d += __shfl_xor_sync(0xffffffffu, d, 1);
            d += __shfl_xor_sync(0xffffffffu, d, 2);
            d += __shfl_xor_sync(0xffffffffu, d, 4);
            d += __shfl_xor_sync(0xffffffffu, d, 8);
            float nm = fmaxf(mx[t], d);
            float corr = __expf(mx[t] - nm);
            float p = __expf(d - nm);
            sum[t] = sum[t] * corr + p;
            o2[t].x = o2[t].x * corr + p * vf.x;
            o2[t].y = o2[t].y * corr + p * vf.y;
            mx[t] = nm;
        }
    }
    __half2* orow = (__half2*)(g_o + row * DMODEL);
    #pragma unroll
    for (int t = 0; t < 4; t++) {
        float inv = 1.0f / sum[t];
        orow[lane + 32 * t] = __floats2half2_rn(o2[t].x * inv, o2[t].y * inv);
    }
}

// ---------------- output head ----------------
__global__ void out_kernel(const float* __restrict__ W_out, const float* __restrict__ b_out,
                           float* __restrict__ out) {
    int b = blockIdx.y;
    int warp = threadIdx.x >> 5;
    int lane = threadIdx.x & 31;
    int j = blockIdx.x * 8 + warp;
    if (j >= NUM_VM) return;
    int row = b * SEQL + NUM_PM + 1 + j;
    float acc = 0.f;
    #pragma unroll
    for (int d = lane; d < DMODEL; d += 32)
        acc += g_x[row * DMODEL + d] * W_out[d];
    #pragma unroll
    for (int o = 16; o > 0; o >>= 1) acc += __shfl_xor_sync(0xffffffffu, acc, o);
    if (lane == 0) out[b * NUM_VM + j] = acc + b_out[0];
}

// ---------------- host launcher ----------------
extern "C" void kernel_launch(void* const* d_in, const int* in_sizes, int n_in,
                              void* d_out, int out_size) {
    const float* vm_states = (const float*)d_in[0];
    const float* num_step  = (const float*)d_in[1];
    const float* pm_states = (const float*)d_in[2];
    const float* W_pm = (const float*)d_in[3];
    const float* b_pm = (const float*)d_in[4];
    const float* W_vm = (const float*)d_in[5];
    const float* b_vm = (const float*)d_in[6];
    const float* critic = (const float*)d_in[7];
    const float* ln1_g = (const float*)d_in[8];
    const float* ln1_b = (const float*)d_in[9];
    const float* Wq = (const float*)d_in[10];
    const float* bq = (const float*)d_in[11];
    const float* Wk = (const float*)d_in[12];
    const float* bk = (const float*)d_in[13];
    const float* Wv = (const float*)d_in[14];
    const float* bv = (const float*)d_in[15];
    const float* Wo = (const float*)d_in[16];
    const float* bo = (const float*)d_in[17];
    const float* ln2_g = (const float*)d_in[18];
    const float* ln2_b = (const float*)d_in[19];
    const float* W1 = (const float*)d_in[20];
    const float* b1 = (const float*)d_in[21];
    const float* W2 = (const float*)d_in[22];
    const float* b2 = (const float*)d_in[23];
    const float* W_out = (const float*)d_in[24];
    const float* b_out = (const float*)d_in[25];
    float* out = (float*)d_out;

    void *ph, *pq, *pk, *pv, *po, *pf, *px;
    void *pWq, *pWk, *pWv, *pWo, *pW1, *pW2;
    cudaGetSymbolAddress(&px, g_x);
    cudaGetSymbolAddress(&ph, g_h);
    cudaGetSymbolAddress(&pq, g_q);
    cudaGetSymbolAddress(&pk, g_k);
    cudaGetSymbolAddress(&pv, g_v);
    cudaGetSymbolAddress(&po, g_o);
    cudaGetSymbolAddress(&pf, g_ffn);
    cudaGetSymbolAddress(&pWq, g_Wqt);
    cudaGetSymbolAddress(&pWk, g_Wkt);
    cudaGetSymbolAddress(&pWv, g_Wvt);
    cudaGetSymbolAddress(&pWo, g_Wot);
    cudaGetSymbolAddress(&pW1, g_W1t);
    cudaGetSymbolAddress(&pW2, g_W2t);
    float* x = (float*)px;
    __half* h = (__half*)ph;
    __half* q = (__half*)pq;
    __half* k = (__half*)pk;
    __half* v = (__half*)pv;
    __half* o = (__half*)po;
    __half* f = (__half*)pf;
    __half* rWq = (__half*)pWq;
    __half* rWk = (__half*)pWk;
    __half* rWv = (__half*)pWv;
    __half* rWo = (__half*)pWo;
    __half* rW1 = (__half*)pW1;
    __half* rW2 = (__half*)pW2;

    cudaFuncSetAttribute(gemm_h, cudaFuncAttributeMaxDynamicSharedMemorySize, GEMM_SMEM_H);

    transpose_all<<<2304, dim3(32, 8)>>>(Wq, Wk, Wv, Wo, W1, W2);

    embed_kernel<<<dim3(SEQL, BATCH), DMODEL>>>(vm_states, num_step, pm_states,
                                                W_pm, b_pm, W_vm, b_vm, critic);
    build_vm<<<(BATCH * NUM_VM + 255) / 256, 256>>>(vm_states);

    const int M = MROWS;
    const int gridM = (M + 127) / 128;              // 82
    dim3 gQKV(DMODEL / 64, gridM, 3);               // (4, 82, 3)
    dim3 g256(DMODEL / 64, gridM, 1);               // (4, 82)
    dim3 g1024(DFF / 64, gridM, 1);                 // (16, 82)
    dim3 gln((MROWS + 7) / 8);
    dim3 gattn((BATCH * SEQL + 7) / 8);

    for (int l = 0; l < NLAYER; l++) {
        ln_kernel<<<gln, 256>>>(ln1_g + l * DMODEL, ln1_b + l * DMODEL);
        gemm_h<<<gQKV, 256, GEMM_SMEM_H>>>(h,
            rWq + l * DMODEL * DMODEL, rWk + l * DMODEL * DMODEL, rWv + l * DMODEL * DMODEL,
            bq + l * DMODEL, bk + l * DMODEL, bv + l * DMODEL,
            q, k, v, nullptr, M, DMODEL, DMODEL, 0, 1);
        attn_kernel<<<gattn, 256>>>();
        gemm_h<<<g256, 256, GEMM_SMEM_H>>>(o,
            rWo + l * DMODEL * DMODEL, rWo + l * DMODEL * DMODEL, rWo + l * DMODEL * DMODEL,
            bo + l * DMODEL, bo + l * DMODEL, bo + l * DMODEL,
            x, x, x, x, M, DMODEL, DMODEL, 0, 0);
        ln_kernel<<<gln, 256>>>(ln2_g + l * DMODEL, ln2_b + l * DMODEL);
        gemm_h<<<g1024, 256, GEMM_SMEM_H>>>(h,
            rW1 + l * DMODEL * DFF, rW1 + l * DMODEL * DFF, rW1 + l * DMODEL * DFF,
            b1 + l * DFF, b1 + l * DFF, b1 + l * DFF,
            f, f, f, nullptr, M, DFF, DMODEL, 1, 1);
        gemm_h<<<g256, 256, GEMM_SMEM_H>>>(f,
            rW2 + l * DFF * DMODEL, rW2 + l * DFF * DMODEL, rW2 + l * DFF * DMODEL,
            b2 + l * DMODEL, b2 + l * DMODEL, b2 + l * DMODEL,
            x, x, x, x, M, DMODEL, DFF, 0, 0);
    }

    out_kernel<<<dim3((NUM_VM + 7) / 8, BATCH), 256>>>(W_out, b_out, out);
}